// round 2
// baseline (speedup 1.0000x reference)
#include <cuda_runtime.h>

#define HID   128
#define NMAX  50000
#define EMAX  600000
#define BMAX  512
#define METAD 27

// ---------------- scratch (device globals; no allocation allowed) -------------
__device__ float g_dinv[NMAX];
__device__ float g_hs [(size_t)NMAX * HID];
__device__ float g_acc[(size_t)NMAX * HID];
__device__ float g_h  [(size_t)NMAX * HID];
__device__ float g_sum[BMAX * HID];
__device__ float g_cnt[BMAX];
__device__ int   g_ei64;     // 1 if edge_index buffer is int64, else 0
__device__ int   g_ba64;     // 1 if batch buffer is int64, else 0

// index fetch honoring runtime-detected dtype (little-endian low word)
__device__ __forceinline__ int fetch_idx(const int* __restrict__ p, size_t i, int is64) {
    return is64 ? p[2 * i] : p[i];
}

// ---------------- dtype detector (1 thread; reads only within min extent) -----
__global__ void detect_kernel(const int* __restrict__ ei, const int* __restrict__ batch,
                              int E, int N) {
    // edge_index: sample odd 32-bit words among first 2E words (always in bounds).
    // int64 data (values < 2^31): odd words all zero. int32 data: uniform [0,N).
    int all_zero = 1;
    for (int k = 0; k < 48; k++) {
        size_t j = (size_t)(((long long)(k + 1) * (E - 2)) / 49);   // j < E-1
        if (ei[2 * j + 1] != 0) { all_zero = 0; break; }
    }
    g_ei64 = all_zero;
    // batch: sorted 0..B-1 over N nodes. Sample odd words in upper half of the
    // first N words (in bounds for both layouts). int32 -> values ~B/2..B-1 != 0.
    all_zero = 1;
    for (int k = 0; k < 48; k++) {
        size_t j = (size_t)(N / 2 + ((long long)k * (N / 2 - 2)) / 48);  // j < N-1
        if (batch[2 * (j / 2) + 1] != 0) { all_zero = 0; break; }
    }
    g_ba64 = all_zero;
}

// ---------------- init: deg=1 (self loop), zero pooling buffers ---------------
__global__ void init_kernel(int N, int B) {
    int i = blockIdx.x * blockDim.x + threadIdx.x;
    if (i < N) g_dinv[i] = 1.0f;
    if (i < B * HID) g_sum[i] = 0.0f;
    if (i < B) g_cnt[i] = 0.0f;
}

__global__ void deg_kernel(const int* __restrict__ ei, int E) {
    int e = blockIdx.x * blockDim.x + threadIdx.x;
    if (e < E) {
        int d = fetch_idx(ei, (size_t)E + e, g_ei64);
        atomicAdd(&g_dinv[d], 1.0f);
    }
}

__global__ void rsqrt_kernel(int N) {
    int i = blockIdx.x * blockDim.x + threadIdx.x;
    if (i < N) g_dinv[i] = rsqrtf(g_dinv[i]);   // deg >= 1 guaranteed by self loop
}

// ---------------- GEMM: hs = acc = dinv[row] * (A @ W)  (A: [M,128], W: [128,128])
// 128x128 block tile, 256 threads, 8x8 microtile, K chunked by 32.
__global__ __launch_bounds__(256, 1)
void gemm_kernel(const float* __restrict__ Aext, const float* __restrict__ W,
                 int M, int use_gh)
{
    __shared__ __align__(16) float As[128 * 36];   // [m][k] pitch 36
    __shared__ __align__(16) float Ws[32 * 128];   // [k][n]

    const float* A = use_gh ? g_h : Aext;
    int tid = threadIdx.x;
    int tx = tid & 15;        // n-tile index
    int ty = tid >> 4;        // m-tile index
    int row0 = blockIdx.x * 128;
    bool full = (row0 + 128 <= M);

    float c[8][8];
#pragma unroll
    for (int i = 0; i < 8; i++)
#pragma unroll
        for (int j = 0; j < 8; j++) c[i][j] = 0.0f;

    for (int kk = 0; kk < 128; kk += 32) {
        // W chunk: rows kk..kk+31 -> Ws[k][n], straight copy (4096 floats)
        {
            const float4* W4 = (const float4*)(W + (size_t)kk * 128);
            float4* Ws4 = (float4*)Ws;
#pragma unroll
            for (int i = 0; i < 4; i++) Ws4[i * 256 + tid] = W4[i * 256 + tid];
        }
        // A chunk: [row0..row0+128) x [kk..kk+32) -> As[m][k]
#pragma unroll
        for (int i = 0; i < 4; i++) {
            int li = i * 256 + tid;          // float4 index, 8 per row
            int m  = li >> 3;
            int k  = (li & 7) << 2;
            float4 v;
            if (full || (row0 + m) < M)
                v = *(const float4*)(A + (size_t)(row0 + m) * 128 + kk + k);
            else
                v = make_float4(0.f, 0.f, 0.f, 0.f);
            *(float4*)(As + m * 36 + k) = v;
        }
        __syncthreads();

#pragma unroll
        for (int k = 0; k < 32; k++) {
            float a[8];
#pragma unroll
            for (int i = 0; i < 8; i++) a[i] = As[(ty * 8 + i) * 36 + k];
            float4 b0 = *(const float4*)(Ws + k * 128 + tx * 8);
            float4 b1 = *(const float4*)(Ws + k * 128 + tx * 8 + 4);
            float b[8] = {b0.x, b0.y, b0.z, b0.w, b1.x, b1.y, b1.z, b1.w};
#pragma unroll
            for (int i = 0; i < 8; i++)
#pragma unroll
                for (int j = 0; j < 8; j++) c[i][j] = fmaf(a[i], b[j], c[i][j]);
        }
        __syncthreads();
    }

    // epilogue: scale by dinv[row]; write hs and acc (acc starts with self-loop term)
#pragma unroll
    for (int i = 0; i < 8; i++) {
        int r = row0 + ty * 8 + i;
        if (r < M) {
            float d = g_dinv[r];
            float4 v0 = make_float4(c[i][0] * d, c[i][1] * d, c[i][2] * d, c[i][3] * d);
            float4 v1 = make_float4(c[i][4] * d, c[i][5] * d, c[i][6] * d, c[i][7] * d);
            size_t off = (size_t)r * 128 + tx * 8;
            *(float4*)(g_hs + off)      = v0;
            *(float4*)(g_hs + off + 4)  = v1;
            *(float4*)(g_acc + off)     = v0;
            *(float4*)(g_acc + off + 4) = v1;
        }
    }
}

// ---------------- edge scatter: acc[dst] += hs[src]  (one warp per edge) ------
__global__ void scatter_kernel(const int* __restrict__ ei, int E) {
    int gid = blockIdx.x * blockDim.x + threadIdx.x;
    int e = gid >> 5;
    if (e >= E) return;
    int lane = gid & 31;
    int is64 = g_ei64;
    int s = fetch_idx(ei, (size_t)e, is64);
    int d = fetch_idx(ei, (size_t)E + e, is64);
    float4 v = *(const float4*)(g_hs + (size_t)s * 128 + lane * 4);
    float* p = g_acc + (size_t)d * 128 + lane * 4;
    atomicAdd(p + 0, v.x);
    atomicAdd(p + 1, v.y);
    atomicAdd(p + 2, v.z);
    atomicAdd(p + 3, v.w);
}

// ---------------- epilogue: h = relu(dinv[row]*acc + b) -----------------------
__global__ void epilogue_kernel(const float* __restrict__ bias, int N) {
    int gid = blockIdx.x * blockDim.x + threadIdx.x;
    int row = gid >> 5;
    if (row >= N) return;
    int lane = gid & 31;
    float d = g_dinv[row];
    size_t off = (size_t)row * 128 + lane * 4;
    float4 v = *(const float4*)(g_acc + off);
    float4 bb = *(const float4*)(bias + lane * 4);
    v.x = fmaxf(fmaf(v.x, d, bb.x), 0.f);
    v.y = fmaxf(fmaf(v.y, d, bb.y), 0.f);
    v.z = fmaxf(fmaf(v.z, d, bb.z), 0.f);
    v.w = fmaxf(fmaf(v.w, d, bb.w), 0.f);
    *(float4*)(g_h + off) = v;
}

// ---------------- mean pool: sum over nodes per graph -------------------------
__global__ void pool_kernel(const int* __restrict__ batch, int N) {
    int gid = blockIdx.x * blockDim.x + threadIdx.x;
    int row = gid >> 5;
    if (row >= N) return;
    int lane = gid & 31;
    int b = fetch_idx(batch, (size_t)row, g_ba64);
    float4 v = *(const float4*)(g_h + (size_t)row * 128 + lane * 4);
    float* p = g_sum + b * 128 + lane * 4;
    atomicAdd(p + 0, v.x);
    atomicAdd(p + 1, v.y);
    atomicAdd(p + 2, v.z);
    atomicAdd(p + 3, v.w);
    if (lane == 0) atomicAdd(&g_cnt[b], 1.0f);
}

// ---------------- MLP head: out[b] = relu([emb, meta] @ Wh1 + bh1) @ Wh2 + bh2
__global__ __launch_bounds__(128)
void head_kernel(const float* __restrict__ meta,
                 const float* __restrict__ Wh1, const float* __restrict__ bh1,
                 const float* __restrict__ Wh2, const float* __restrict__ bh2,
                 float* __restrict__ out)
{
    int b = blockIdx.x;
    int j = threadIdx.x;   // 128 threads
    __shared__ float zin[HID + METAD];
    __shared__ float red[128];

    float inv = 1.0f / fmaxf(g_cnt[b], 1.0f);
    zin[j] = g_sum[b * HID + j] * inv;
    if (j < METAD) zin[HID + j] = meta[b * METAD + j];
    __syncthreads();

    float acc = bh1[j];
#pragma unroll
    for (int k = 0; k < HID + METAD; k++)
        acc = fmaf(zin[k], Wh1[k * HID + j], acc);
    red[j] = fmaxf(acc, 0.0f) * Wh2[j];
    __syncthreads();
#pragma unroll
    for (int s = 64; s > 0; s >>= 1) {
        if (j < s) red[j] += red[j + s];
        __syncthreads();
    }
    if (j == 0) out[b] = red[0] + bh2[0];
}

// ------------------------------------------------------------------------------
extern "C" void kernel_launch(void* const* d_in, const int* in_sizes, int n_in,
                              void* d_out, int out_size)
{
    const float* x     = (const float*)d_in[0];
    const int*   ei    = (const int*)d_in[1];
    const int*   batch = (const int*)d_in[2];
    const float* meta  = (const float*)d_in[3];
    const float* W1 = (const float*)d_in[4];  const float* b1 = (const float*)d_in[5];
    const float* W2 = (const float*)d_in[6];  const float* b2 = (const float*)d_in[7];
    const float* W3 = (const float*)d_in[8];  const float* b3 = (const float*)d_in[9];
    const float* Wh1 = (const float*)d_in[10]; const float* bh1 = (const float*)d_in[11];
    const float* Wh2 = (const float*)d_in[12]; const float* bh2 = (const float*)d_in[13];
    float* out = (float*)d_out;

    int N = in_sizes[0] / HID;
    int E = in_sizes[1] / 2;
    int B = in_sizes[3] / METAD;

    detect_kernel<<<1, 1>>>(ei, batch, E, N);

    int initN = (N > B * HID) ? N : B * HID;
    init_kernel <<<(initN + 255) / 256, 256>>>(N, B);
    deg_kernel  <<<(E + 255) / 256, 256>>>(ei, E);
    rsqrt_kernel<<<(N + 255) / 256, 256>>>(N);

    int gblocks = (N + 127) / 128;
    int sblocks = (int)(((long long)E * 32 + 255) / 256);
    int nblocks = (int)(((long long)N * 32 + 255) / 256);

    // layer 1
    gemm_kernel    <<<gblocks, 256>>>(x, W1, N, 0);
    scatter_kernel <<<sblocks, 256>>>(ei, E);
    epilogue_kernel<<<nblocks, 256>>>(b1, N);
    // layer 2
    gemm_kernel    <<<gblocks, 256>>>(nullptr, W2, N, 1);
    scatter_kernel <<<sblocks, 256>>>(ei, E);
    epilogue_kernel<<<nblocks, 256>>>(b2, N);
    // layer 3
    gemm_kernel    <<<gblocks, 256>>>(nullptr, W3, N, 1);
    scatter_kernel <<<sblocks, 256>>>(ei, E);
    epilogue_kernel<<<nblocks, 256>>>(b3, N);

    // pooling + head
    pool_kernel<<<nblocks, 256>>>(batch, N);
    head_kernel<<<B, 128>>>(meta, Wh1, bh1, Wh2, bh2, out);
}

// round 3
// speedup vs baseline: 2.6651x; 2.6651x over previous
#include <cuda_runtime.h>

#define HID   128
#define NMAX  50000
#define EMAX  600000
#define BMAX  512
#define METAD 27

// ---------------- scratch (device globals; no allocation allowed) -------------
__device__ float g_dinv[NMAX];
__device__ float g_hs [(size_t)NMAX * HID];
__device__ float g_h  [(size_t)NMAX * HID];
__device__ float g_sum[BMAX * HID];
__device__ float g_cnt[BMAX];
__device__ int   g_indeg[NMAX];     // in-degree histogram (excl self loop)
__device__ int   g_off  [NMAX];     // CSR offsets (exclusive scan of indeg)
__device__ int   g_cur  [NMAX];     // fill cursors
__device__ int   g_bsum [256];      // scan block sums
__device__ int   g_srcs [EMAX];     // src indices sorted by dst
__device__ int   g_ei64;            // 1 if edge_index buffer is int64
__device__ int   g_ba64;            // 1 if batch buffer is int64

__device__ __forceinline__ int fetch_idx(const int* __restrict__ p, size_t i, int is64) {
    return is64 ? p[2 * i] : p[i];
}

// ---------------- dtype detector (1 thread; reads only within min extent) -----
__global__ void detect_kernel(const int* __restrict__ ei, const int* __restrict__ batch,
                              int E, int N) {
    int all_zero = 1;
    for (int k = 0; k < 48; k++) {
        size_t j = (size_t)(((long long)(k + 1) * (E - 2)) / 49);
        if (ei[2 * j + 1] != 0) { all_zero = 0; break; }
    }
    g_ei64 = all_zero;
    all_zero = 1;
    for (int k = 0; k < 48; k++) {
        size_t j = (size_t)(N / 2 + ((long long)k * (N / 2 - 2)) / 48);
        if (batch[2 * (j / 2) + 1] != 0) { all_zero = 0; break; }
    }
    g_ba64 = all_zero;
}

// ---------------- init: zero histograms / cursors / pooling buffers -----------
__global__ void init_kernel(int N, int B) {
    int i = blockIdx.x * blockDim.x + threadIdx.x;
    if (i < N) { g_indeg[i] = 0; g_cur[i] = 0; }
    if (i < B * HID) g_sum[i] = 0.0f;
    if (i < B) g_cnt[i] = 0.0f;
}

// ---------------- in-degree histogram ------------------------------------------
__global__ void hist_kernel(const int* __restrict__ ei, int E) {
    int e = blockIdx.x * blockDim.x + threadIdx.x;
    if (e < E) atomicAdd(&g_indeg[fetch_idx(ei, (size_t)E + e, g_ei64)], 1);
}

// ---------------- exclusive scan of indeg -> off (3 phases) -------------------
__global__ void scan_block_kernel(int N) {
    __shared__ int sh[256];
    int i = blockIdx.x * 256 + threadIdx.x;
    int v = (i < N) ? g_indeg[i] : 0;
    sh[threadIdx.x] = v;
    __syncthreads();
#pragma unroll
    for (int s = 1; s < 256; s <<= 1) {
        int t = (threadIdx.x >= s) ? sh[threadIdx.x - s] : 0;
        __syncthreads();
        sh[threadIdx.x] += t;
        __syncthreads();
    }
    if (i < N) g_off[i] = sh[threadIdx.x] - v;   // exclusive
    if (threadIdx.x == 255) g_bsum[blockIdx.x] = sh[255];
}

__global__ void scan_tops_kernel(int nb) {
    if (threadIdx.x == 0) {
        int run = 0;
        for (int b = 0; b < nb; b++) { int t = g_bsum[b]; g_bsum[b] = run; run += t; }
    }
}

__global__ void scan_add_kernel(int N) {
    int i = blockIdx.x * 256 + threadIdx.x;
    if (i < N) {
        g_off[i] += g_bsum[blockIdx.x];
        g_dinv[i] = rsqrtf((float)(g_indeg[i] + 1));   // deg incl. self loop
    }
}

// ---------------- fill: srcs sorted by dst --------------------------------------
__global__ void fill_kernel(const int* __restrict__ ei, int E) {
    int e = blockIdx.x * blockDim.x + threadIdx.x;
    if (e >= E) return;
    int is64 = g_ei64;
    int s = fetch_idx(ei, (size_t)e, is64);
    int d = fetch_idx(ei, (size_t)E + e, is64);
    int pos = g_off[d] + atomicAdd(&g_cur[d], 1);
    g_srcs[pos] = s;
}

// ---------------- GEMM: hs = dinv[row] * (A @ W)  (A:[M,128], W:[128,128]) ----
__global__ __launch_bounds__(256, 1)
void gemm_kernel(const float* __restrict__ Aext, const float* __restrict__ W,
                 int M, int use_gh)
{
    __shared__ __align__(16) float As[128 * 36];
    __shared__ __align__(16) float Ws[32 * 128];

    const float* A = use_gh ? g_h : Aext;
    int tid = threadIdx.x;
    int tx = tid & 15;
    int ty = tid >> 4;
    int row0 = blockIdx.x * 128;
    bool full = (row0 + 128 <= M);

    float c[8][8];
#pragma unroll
    for (int i = 0; i < 8; i++)
#pragma unroll
        for (int j = 0; j < 8; j++) c[i][j] = 0.0f;

    for (int kk = 0; kk < 128; kk += 32) {
        {
            const float4* W4 = (const float4*)(W + (size_t)kk * 128);
            float4* Ws4 = (float4*)Ws;
#pragma unroll
            for (int i = 0; i < 4; i++) Ws4[i * 256 + tid] = W4[i * 256 + tid];
        }
#pragma unroll
        for (int i = 0; i < 4; i++) {
            int li = i * 256 + tid;
            int m  = li >> 3;
            int k  = (li & 7) << 2;
            float4 v;
            if (full || (row0 + m) < M)
                v = *(const float4*)(A + (size_t)(row0 + m) * 128 + kk + k);
            else
                v = make_float4(0.f, 0.f, 0.f, 0.f);
            *(float4*)(As + m * 36 + k) = v;
        }
        __syncthreads();

#pragma unroll
        for (int k = 0; k < 32; k++) {
            float a[8];
#pragma unroll
            for (int i = 0; i < 8; i++) a[i] = As[(ty * 8 + i) * 36 + k];
            float4 b0 = *(const float4*)(Ws + k * 128 + tx * 8);
            float4 b1 = *(const float4*)(Ws + k * 128 + tx * 8 + 4);
            float b[8] = {b0.x, b0.y, b0.z, b0.w, b1.x, b1.y, b1.z, b1.w};
#pragma unroll
            for (int i = 0; i < 8; i++)
#pragma unroll
                for (int j = 0; j < 8; j++) c[i][j] = fmaf(a[i], b[j], c[i][j]);
        }
        __syncthreads();
    }

#pragma unroll
    for (int i = 0; i < 8; i++) {
        int r = row0 + ty * 8 + i;
        if (r < M) {
            float d = g_dinv[r];
            size_t off = (size_t)r * 128 + tx * 8;
            *(float4*)(g_hs + off)     = make_float4(c[i][0]*d, c[i][1]*d, c[i][2]*d, c[i][3]*d);
            *(float4*)(g_hs + off + 4) = make_float4(c[i][4]*d, c[i][5]*d, c[i][6]*d, c[i][7]*d);
        }
    }
}

// ---------------- gather: h[r] = relu(dinv[r]*(hs[r] + sum_in hs[src]) + b) ----
// one warp per row; optional fused mean-pool accumulation (layer 3)
__global__ void gather_kernel(const float* __restrict__ bias, int N,
                              const int* __restrict__ batch, int do_pool)
{
    int gid = blockIdx.x * blockDim.x + threadIdx.x;
    int row = gid >> 5;
    if (row >= N) return;
    int lane = gid & 31;

    const float4* hs4 = (const float4*)g_hs;
    int beg = g_off[row];
    int cnt = g_indeg[row];

    float4 a = hs4[(size_t)row * 32 + lane];   // self-loop term
    int k = 0;
    for (; k + 2 <= cnt; k += 2) {
        int s0 = g_srcs[beg + k];
        int s1 = g_srcs[beg + k + 1];
        float4 v0 = hs4[(size_t)s0 * 32 + lane];
        float4 v1 = hs4[(size_t)s1 * 32 + lane];
        a.x += v0.x + v1.x; a.y += v0.y + v1.y;
        a.z += v0.z + v1.z; a.w += v0.w + v1.w;
    }
    if (k < cnt) {
        int s0 = g_srcs[beg + k];
        float4 v0 = hs4[(size_t)s0 * 32 + lane];
        a.x += v0.x; a.y += v0.y; a.z += v0.z; a.w += v0.w;
    }

    float dv = g_dinv[row];
    float4 bb = ((const float4*)bias)[lane];
    a.x = fmaxf(fmaf(a.x, dv, bb.x), 0.f);
    a.y = fmaxf(fmaf(a.y, dv, bb.y), 0.f);
    a.z = fmaxf(fmaf(a.z, dv, bb.z), 0.f);
    a.w = fmaxf(fmaf(a.w, dv, bb.w), 0.f);

    if (!do_pool) {
        *(float4*)(g_h + (size_t)row * 128 + lane * 4) = a;
    } else {
        int b = fetch_idx(batch, (size_t)row, g_ba64);
        float* p = g_sum + b * 128 + lane * 4;
        atomicAdd(p + 0, a.x);
        atomicAdd(p + 1, a.y);
        atomicAdd(p + 2, a.z);
        atomicAdd(p + 3, a.w);
        if (lane == 0) atomicAdd(&g_cnt[b], 1.0f);
    }
}

// ---------------- MLP head ------------------------------------------------------
__global__ __launch_bounds__(128)
void head_kernel(const float* __restrict__ meta,
                 const float* __restrict__ Wh1, const float* __restrict__ bh1,
                 const float* __restrict__ Wh2, const float* __restrict__ bh2,
                 float* __restrict__ out)
{
    int b = blockIdx.x;
    int j = threadIdx.x;
    __shared__ float zin[HID + METAD];
    __shared__ float red[128];

    float inv = 1.0f / fmaxf(g_cnt[b], 1.0f);
    zin[j] = g_sum[b * HID + j] * inv;
    if (j < METAD) zin[HID + j] = meta[b * METAD + j];
    __syncthreads();

    float acc = bh1[j];
#pragma unroll
    for (int k = 0; k < HID + METAD; k++)
        acc = fmaf(zin[k], Wh1[k * HID + j], acc);
    red[j] = fmaxf(acc, 0.0f) * Wh2[j];
    __syncthreads();
#pragma unroll
    for (int s = 64; s > 0; s >>= 1) {
        if (j < s) red[j] += red[j + s];
        __syncthreads();
    }
    if (j == 0) out[b] = red[0] + bh2[0];
}

// --------------------------------------------------------------------------------
extern "C" void kernel_launch(void* const* d_in, const int* in_sizes, int n_in,
                              void* d_out, int out_size)
{
    const float* x     = (const float*)d_in[0];
    const int*   ei    = (const int*)d_in[1];
    const int*   batch = (const int*)d_in[2];
    const float* meta  = (const float*)d_in[3];
    const float* W1 = (const float*)d_in[4];  const float* b1 = (const float*)d_in[5];
    const float* W2 = (const float*)d_in[6];  const float* b2 = (const float*)d_in[7];
    const float* W3 = (const float*)d_in[8];  const float* b3 = (const float*)d_in[9];
    const float* Wh1 = (const float*)d_in[10]; const float* bh1 = (const float*)d_in[11];
    const float* Wh2 = (const float*)d_in[12]; const float* bh2 = (const float*)d_in[13];
    float* out = (float*)d_out;

    int N = in_sizes[0] / HID;
    int E = in_sizes[1] / 2;
    int B = in_sizes[3] / METAD;

    detect_kernel<<<1, 1>>>(ei, batch, E, N);

    int initN = (N > B * HID) ? N : B * HID;
    init_kernel<<<(initN + 255) / 256, 256>>>(N, B);
    hist_kernel<<<(E + 255) / 256, 256>>>(ei, E);

    int nscan = (N + 255) / 256;
    scan_block_kernel<<<nscan, 256>>>(N);
    scan_tops_kernel <<<1, 32>>>(nscan);
    scan_add_kernel  <<<nscan, 256>>>(N);
    fill_kernel      <<<(E + 255) / 256, 256>>>(ei, E);

    int gblocks = (N + 127) / 128;
    int wblocks = (int)(((long long)N * 32 + 255) / 256);

    // layer 1
    gemm_kernel  <<<gblocks, 256>>>(x, W1, N, 0);
    gather_kernel<<<wblocks, 256>>>(b1, N, batch, 0);
    // layer 2
    gemm_kernel  <<<gblocks, 256>>>(nullptr, W2, N, 1);
    gather_kernel<<<wblocks, 256>>>(b2, N, batch, 0);
    // layer 3 (fused mean-pool accumulation)
    gemm_kernel  <<<gblocks, 256>>>(nullptr, W3, N, 1);
    gather_kernel<<<wblocks, 256>>>(b3, N, batch, 1);

    head_kernel<<<B, 128>>>(meta, Wh1, bh1, Wh2, bh2, out);
}

// round 4
// speedup vs baseline: 2.8269x; 1.0607x over previous
#include <cuda_runtime.h>

#define HID   128
#define NMAX  50000
#define EMAX  600000
#define BMAX  512
#define METAD 27

// ---------------- scratch (device globals; no allocation allowed) -------------
__device__ float g_dinv[NMAX];
__device__ float g_hs [(size_t)NMAX * HID];
__device__ float g_h  [(size_t)NMAX * HID];
__device__ float g_sum[BMAX * HID];
__device__ float g_cnt[BMAX];
__device__ int   g_indeg[NMAX];     // in-degree histogram (excl self loop)
__device__ int   g_off  [NMAX];     // CSR offsets (exclusive scan of indeg)
__device__ int   g_cur  [NMAX];     // fill cursors
__device__ int   g_bsum [256];      // scan block sums
__device__ int   g_srcs [EMAX];     // src indices sorted by dst
__device__ int   g_ei64;            // 1 if edge_index buffer is int64
__device__ int   g_ba64;            // 1 if batch buffer is int64

__device__ __forceinline__ int fetch_idx(const int* __restrict__ p, size_t i, int is64) {
    return is64 ? p[2 * i] : p[i];
}

// ---------------- init (+ dtype detect on thread 0 of block 0) ----------------
__global__ void init_kernel(const int* __restrict__ ei, const int* __restrict__ batch,
                            int E, int N, int B) {
    int i = blockIdx.x * blockDim.x + threadIdx.x;
    if (i == 0) {
        // edge_index: sample odd 32-bit words among first 2E words (in bounds).
        int all_zero = 1;
        for (int k = 0; k < 48; k++) {
            size_t j = (size_t)(((long long)(k + 1) * (E - 2)) / 49);
            if (ei[2 * j + 1] != 0) { all_zero = 0; break; }
        }
        g_ei64 = all_zero;
        all_zero = 1;
        for (int k = 0; k < 48; k++) {
            size_t j = (size_t)(N / 2 + ((long long)k * (N / 2 - 2)) / 48);
            if (batch[2 * (j / 2) + 1] != 0) { all_zero = 0; break; }
        }
        g_ba64 = all_zero;
    }
    if (i < N) { g_indeg[i] = 0; g_cur[i] = 0; }
    if (i < B * HID) g_sum[i] = 0.0f;
    if (i < B) g_cnt[i] = 0.0f;
}

// ---------------- in-degree histogram ------------------------------------------
__global__ void hist_kernel(const int* __restrict__ ei, int E) {
    int e = blockIdx.x * blockDim.x + threadIdx.x;
    if (e < E) atomicAdd(&g_indeg[fetch_idx(ei, (size_t)E + e, g_ei64)], 1);
}

// ---------------- scan phase 1: per-block exclusive scan ----------------------
__global__ void scan_block_kernel(int N) {
    __shared__ int sh[256];
    int i = blockIdx.x * 256 + threadIdx.x;
    int v = (i < N) ? g_indeg[i] : 0;
    sh[threadIdx.x] = v;
    __syncthreads();
#pragma unroll
    for (int s = 1; s < 256; s <<= 1) {
        int t = (threadIdx.x >= s) ? sh[threadIdx.x - s] : 0;
        __syncthreads();
        sh[threadIdx.x] += t;
        __syncthreads();
    }
    if (i < N) g_off[i] = sh[threadIdx.x] - v;   // exclusive
    if (threadIdx.x == 255) g_bsum[blockIdx.x] = sh[255];
}

// ---------------- scan phase 2: add block-prefix, compute dinv ----------------
__global__ void scan_add_kernel(int N) {
    __shared__ int base_sh;
    if (threadIdx.x < 32) {
        int run = 0;
        for (int b = threadIdx.x; b < blockIdx.x; b += 32) run += g_bsum[b];
#pragma unroll
        for (int s = 16; s > 0; s >>= 1) run += __shfl_down_sync(0xffffffffu, run, s);
        if (threadIdx.x == 0) base_sh = run;
    }
    __syncthreads();
    int i = blockIdx.x * 256 + threadIdx.x;
    if (i < N) {
        g_off[i] += base_sh;
        g_dinv[i] = rsqrtf((float)(g_indeg[i] + 1));   // deg incl. self loop
    }
}

// ---------------- fill: srcs sorted by dst --------------------------------------
__global__ void fill_kernel(const int* __restrict__ ei, int E) {
    int e = blockIdx.x * blockDim.x + threadIdx.x;
    if (e >= E) return;
    int is64 = g_ei64;
    int s = fetch_idx(ei, (size_t)e, is64);
    int d = fetch_idx(ei, (size_t)E + e, is64);
    int pos = g_off[d] + atomicAdd(&g_cur[d], 1);
    g_srcs[pos] = s;
}

// ---------------- GEMM: hs = dinv[row] * (A @ W)  (A:[M,128], W:[128,128]) ----
// 128x128 tile, 256 threads, 8x8 microtile; 2 blocks/SM for latency hiding.
__global__ __launch_bounds__(256, 2)
void gemm_kernel(const float* __restrict__ Aext, const float* __restrict__ W,
                 int M, int use_gh)
{
    __shared__ __align__(16) float As[128 * 36];
    __shared__ __align__(16) float Ws[32 * 128];

    const float* A = use_gh ? g_h : Aext;
    int tid = threadIdx.x;
    int tx = tid & 15;
    int ty = tid >> 4;
    int row0 = blockIdx.x * 128;
    bool full = (row0 + 128 <= M);

    float c[8][8];
#pragma unroll
    for (int i = 0; i < 8; i++)
#pragma unroll
        for (int j = 0; j < 8; j++) c[i][j] = 0.0f;

    for (int kk = 0; kk < 128; kk += 32) {
        {
            const float4* W4 = (const float4*)(W + (size_t)kk * 128);
            float4* Ws4 = (float4*)Ws;
#pragma unroll
            for (int i = 0; i < 4; i++) Ws4[i * 256 + tid] = W4[i * 256 + tid];
        }
#pragma unroll
        for (int i = 0; i < 4; i++) {
            int li = i * 256 + tid;
            int m  = li >> 3;
            int k  = (li & 7) << 2;
            float4 v;
            if (full || (row0 + m) < M)
                v = *(const float4*)(A + (size_t)(row0 + m) * 128 + kk + k);
            else
                v = make_float4(0.f, 0.f, 0.f, 0.f);
            *(float4*)(As + m * 36 + k) = v;
        }
        __syncthreads();

#pragma unroll
        for (int k = 0; k < 32; k++) {
            float a[8];
#pragma unroll
            for (int i = 0; i < 8; i++) a[i] = As[(ty * 8 + i) * 36 + k];
            float4 b0 = *(const float4*)(Ws + k * 128 + tx * 8);
            float4 b1 = *(const float4*)(Ws + k * 128 + tx * 8 + 4);
            float b[8] = {b0.x, b0.y, b0.z, b0.w, b1.x, b1.y, b1.z, b1.w};
#pragma unroll
            for (int i = 0; i < 8; i++)
#pragma unroll
                for (int j = 0; j < 8; j++) c[i][j] = fmaf(a[i], b[j], c[i][j]);
        }
        __syncthreads();
    }

#pragma unroll
    for (int i = 0; i < 8; i++) {
        int r = row0 + ty * 8 + i;
        if (r < M) {
            float d = g_dinv[r];
            size_t off = (size_t)r * 128 + tx * 8;
            *(float4*)(g_hs + off)     = make_float4(c[i][0]*d, c[i][1]*d, c[i][2]*d, c[i][3]*d);
            *(float4*)(g_hs + off + 4) = make_float4(c[i][4]*d, c[i][5]*d, c[i][6]*d, c[i][7]*d);
        }
    }
}

// ---------------- gather: h[r] = relu(dinv[r]*(hs[r] + sum_in hs[src]) + b) ----
// one warp per row; optional fused mean-pool accumulation (layer 3)
__global__ void gather_kernel(const float* __restrict__ bias, int N,
                              const int* __restrict__ batch, int do_pool)
{
    int gid = blockIdx.x * blockDim.x + threadIdx.x;
    int row = gid >> 5;
    if (row >= N) return;
    int lane = gid & 31;

    const float4* hs4 = (const float4*)g_hs;
    int beg = g_off[row];
    int cnt = g_indeg[row];

    float4 a = hs4[(size_t)row * 32 + lane];   // self-loop term
    int k = 0;
    for (; k + 2 <= cnt; k += 2) {
        int s0 = g_srcs[beg + k];
        int s1 = g_srcs[beg + k + 1];
        float4 v0 = hs4[(size_t)s0 * 32 + lane];
        float4 v1 = hs4[(size_t)s1 * 32 + lane];
        a.x += v0.x + v1.x; a.y += v0.y + v1.y;
        a.z += v0.z + v1.z; a.w += v0.w + v1.w;
    }
    if (k < cnt) {
        int s0 = g_srcs[beg + k];
        float4 v0 = hs4[(size_t)s0 * 32 + lane];
        a.x += v0.x; a.y += v0.y; a.z += v0.z; a.w += v0.w;
    }

    float dv = g_dinv[row];
    float4 bb = ((const float4*)bias)[lane];
    a.x = fmaxf(fmaf(a.x, dv, bb.x), 0.f);
    a.y = fmaxf(fmaf(a.y, dv, bb.y), 0.f);
    a.z = fmaxf(fmaf(a.z, dv, bb.z), 0.f);
    a.w = fmaxf(fmaf(a.w, dv, bb.w), 0.f);

    if (!do_pool) {
        *(float4*)(g_h + (size_t)row * 128 + lane * 4) = a;
    } else {
        int b = fetch_idx(batch, (size_t)row, g_ba64);
        float* p = g_sum + b * 128 + lane * 4;
        atomicAdd(p + 0, a.x);
        atomicAdd(p + 1, a.y);
        atomicAdd(p + 2, a.z);
        atomicAdd(p + 3, a.w);
        if (lane == 0) atomicAdd(&g_cnt[b], 1.0f);
    }
}

// ---------------- MLP head ------------------------------------------------------
__global__ __launch_bounds__(128)
void head_kernel(const float* __restrict__ meta,
                 const float* __restrict__ Wh1, const float* __restrict__ bh1,
                 const float* __restrict__ Wh2, const float* __restrict__ bh2,
                 float* __restrict__ out)
{
    int b = blockIdx.x;
    int j = threadIdx.x;
    __shared__ float zin[HID + METAD];
    __shared__ float red[128];

    float inv = 1.0f / fmaxf(g_cnt[b], 1.0f);
    zin[j] = g_sum[b * HID + j] * inv;
    if (j < METAD) zin[HID + j] = meta[b * METAD + j];
    __syncthreads();

    float acc = bh1[j];
#pragma unroll
    for (int k = 0; k < HID + METAD; k++)
        acc = fmaf(zin[k], Wh1[k * HID + j], acc);
    red[j] = fmaxf(acc, 0.0f) * Wh2[j];
    __syncthreads();
#pragma unroll
    for (int s = 64; s > 0; s >>= 1) {
        if (j < s) red[j] += red[j + s];
        __syncthreads();
    }
    if (j == 0) out[b] = red[0] + bh2[0];
}

// --------------------------------------------------------------------------------
extern "C" void kernel_launch(void* const* d_in, const int* in_sizes, int n_in,
                              void* d_out, int out_size)
{
    const float* x     = (const float*)d_in[0];
    const int*   ei    = (const int*)d_in[1];
    const int*   batch = (const int*)d_in[2];
    const float* meta  = (const float*)d_in[3];
    const float* W1 = (const float*)d_in[4];  const float* b1 = (const float*)d_in[5];
    const float* W2 = (const float*)d_in[6];  const float* b2 = (const float*)d_in[7];
    const float* W3 = (const float*)d_in[8];  const float* b3 = (const float*)d_in[9];
    const float* Wh1 = (const float*)d_in[10]; const float* bh1 = (const float*)d_in[11];
    const float* Wh2 = (const float*)d_in[12]; const float* bh2 = (const float*)d_in[13];
    float* out = (float*)d_out;

    int N = in_sizes[0] / HID;
    int E = in_sizes[1] / 2;
    int B = in_sizes[3] / METAD;

    int initN = (N > B * HID) ? N : B * HID;
    init_kernel<<<(initN + 255) / 256, 256>>>(ei, batch, E, N, B);
    hist_kernel<<<(E + 255) / 256, 256>>>(ei, E);

    int nscan = (N + 255) / 256;
    scan_block_kernel<<<nscan, 256>>>(N);
    scan_add_kernel  <<<nscan, 256>>>(N);
    fill_kernel      <<<(E + 255) / 256, 256>>>(ei, E);

    int gblocks = (N + 127) / 128;
    int wblocks = (int)(((long long)N * 32 + 255) / 256);

    // layer 1
    gemm_kernel  <<<gblocks, 256>>>(x, W1, N, 0);
    gather_kernel<<<wblocks, 256>>>(b1, N, batch, 0);
    // layer 2
    gemm_kernel  <<<gblocks, 256>>>(nullptr, W2, N, 1);
    gather_kernel<<<wblocks, 256>>>(b2, N, batch, 0);
    // layer 3 (fused mean-pool accumulation)
    gemm_kernel  <<<gblocks, 256>>>(nullptr, W3, N, 1);
    gather_kernel<<<wblocks, 256>>>(b3, N, batch, 1);

    head_kernel<<<B, 128>>>(meta, Wh1, bh1, Wh2, bh2, out);
}

// round 5
// speedup vs baseline: 3.0001x; 1.0613x over previous
#include <cuda_runtime.h>

#define HID   128
#define NMAX  50000
#define EMAX  600000
#define BMAX  512
#define METAD 27

typedef unsigned long long u64t;

// ---------------- scratch (device globals; no allocation allowed) -------------
__device__ float g_dinv[NMAX];
__device__ float g_hs [(size_t)NMAX * HID];
__device__ float g_h  [(size_t)NMAX * HID];
__device__ float g_sum[BMAX * HID];
__device__ float g_cnt[BMAX];
__device__ int   g_indeg[NMAX];
__device__ int   g_off  [NMAX];
__device__ int   g_cur  [NMAX];
__device__ int   g_bsum [256];
__device__ int   g_srcs [EMAX];
__device__ int   g_ei64;
__device__ int   g_ba64;

__device__ __forceinline__ int fetch_idx(const int* __restrict__ p, size_t i, int is64) {
    return is64 ? p[2 * i] : p[i];
}

// ---------------- f32x2 packed helpers ----------------------------------------
__device__ __forceinline__ u64t pack2(float v) {
    u64t r;
    asm("mov.b64 %0, {%1, %1};" : "=l"(r) : "r"(__float_as_uint(v)));
    return r;
}
__device__ __forceinline__ void fma2(u64t& c, u64t a, u64t b) {
    asm("fma.rn.f32x2 %0, %1, %2, %0;" : "+l"(c) : "l"(a), "l"(b));
}
__device__ __forceinline__ u64t mul2(u64t a, u64t b) {
    u64t r;
    asm("mul.rn.f32x2 %0, %1, %2;" : "=l"(r) : "l"(a), "l"(b));
    return r;
}

// ---------------- init (+ dtype detect on thread 0 of block 0) ----------------
__global__ void init_kernel(const int* __restrict__ ei, const int* __restrict__ batch,
                            int E, int N, int B) {
    int i = blockIdx.x * blockDim.x + threadIdx.x;
    if (i == 0) {
        int all_zero = 1;
        for (int k = 0; k < 48; k++) {
            size_t j = (size_t)(((long long)(k + 1) * (E - 2)) / 49);
            if (ei[2 * j + 1] != 0) { all_zero = 0; break; }
        }
        g_ei64 = all_zero;
        all_zero = 1;
        for (int k = 0; k < 48; k++) {
            size_t j = (size_t)(N / 2 + ((long long)k * (N / 2 - 2)) / 48);
            if (batch[2 * (j / 2) + 1] != 0) { all_zero = 0; break; }
        }
        g_ba64 = all_zero;
    }
    if (i < N) { g_indeg[i] = 0; g_cur[i] = 0; }
    if (i < B * HID) g_sum[i] = 0.0f;
    if (i < B) g_cnt[i] = 0.0f;
}

// ---------------- in-degree histogram ------------------------------------------
__global__ void hist_kernel(const int* __restrict__ ei, int E) {
    int e = blockIdx.x * blockDim.x + threadIdx.x;
    if (e < E) atomicAdd(&g_indeg[fetch_idx(ei, (size_t)E + e, g_ei64)], 1);
}

// ---------------- scan phase 1: per-block exclusive scan ----------------------
__global__ void scan_block_kernel(int N) {
    __shared__ int sh[256];
    int i = blockIdx.x * 256 + threadIdx.x;
    int v = (i < N) ? g_indeg[i] : 0;
    sh[threadIdx.x] = v;
    __syncthreads();
#pragma unroll
    for (int s = 1; s < 256; s <<= 1) {
        int t = (threadIdx.x >= s) ? sh[threadIdx.x - s] : 0;
        __syncthreads();
        sh[threadIdx.x] += t;
        __syncthreads();
    }
    if (i < N) g_off[i] = sh[threadIdx.x] - v;
    if (threadIdx.x == 255) g_bsum[blockIdx.x] = sh[255];
}

// ---------------- scan phase 2: add block-prefix, compute dinv ----------------
__global__ void scan_add_kernel(int N) {
    __shared__ int base_sh;
    if (threadIdx.x < 32) {
        int run = 0;
        for (int b = threadIdx.x; b < blockIdx.x; b += 32) run += g_bsum[b];
#pragma unroll
        for (int s = 16; s > 0; s >>= 1) run += __shfl_down_sync(0xffffffffu, run, s);
        if (threadIdx.x == 0) base_sh = run;
    }
    __syncthreads();
    int i = blockIdx.x * 256 + threadIdx.x;
    if (i < N) {
        g_off[i] += base_sh;
        g_dinv[i] = rsqrtf((float)(g_indeg[i] + 1));
    }
}

// ---------------- fill: srcs sorted by dst --------------------------------------
__global__ void fill_kernel(const int* __restrict__ ei, int E) {
    int e = blockIdx.x * blockDim.x + threadIdx.x;
    if (e >= E) return;
    int is64 = g_ei64;
    int s = fetch_idx(ei, (size_t)e, is64);
    int d = fetch_idx(ei, (size_t)E + e, is64);
    int pos = g_off[d] + atomicAdd(&g_cur[d], 1);
    g_srcs[pos] = s;
}

// ---------------- GEMM: hs = dinv[row] * (A @ W)  (A:[M,128], W:[128,128]) ----
// 128x128 tile, 256 threads, 8x8 microtile computed as 8x4 f32x2 (FFMA2).
__global__ __launch_bounds__(256, 2)
void gemm_kernel(const float* __restrict__ Aext, const float* __restrict__ W,
                 int M, int use_gh)
{
    __shared__ __align__(16) float As[128 * 36];
    __shared__ __align__(16) float Ws[32 * 128];

    const float* A = use_gh ? g_h : Aext;
    int tid = threadIdx.x;
    int tx = tid & 15;
    int ty = tid >> 4;
    int row0 = blockIdx.x * 128;
    bool full = (row0 + 128 <= M);

    u64t c2[8][4];
#pragma unroll
    for (int i = 0; i < 8; i++)
#pragma unroll
        for (int j = 0; j < 4; j++) c2[i][j] = 0ull;

    for (int kk = 0; kk < 128; kk += 32) {
        {
            const float4* W4 = (const float4*)(W + (size_t)kk * 128);
            float4* Ws4 = (float4*)Ws;
#pragma unroll
            for (int i = 0; i < 4; i++) Ws4[i * 256 + tid] = W4[i * 256 + tid];
        }
#pragma unroll
        for (int i = 0; i < 4; i++) {
            int li = i * 256 + tid;
            int m  = li >> 3;
            int k  = (li & 7) << 2;
            float4 v;
            if (full || (row0 + m) < M)
                v = *(const float4*)(A + (size_t)(row0 + m) * 128 + kk + k);
            else
                v = make_float4(0.f, 0.f, 0.f, 0.f);
            *(float4*)(As + m * 36 + k) = v;
        }
        __syncthreads();

#pragma unroll
        for (int k = 0; k < 32; k++) {
            // B pairs straight from LDS.128 (already packed as f32x2 halves)
            ulonglong2 q0 = *(const ulonglong2*)(Ws + k * 128 + tx * 8);
            ulonglong2 q1 = *(const ulonglong2*)(Ws + k * 128 + tx * 8 + 4);
            u64t b2[4] = {q0.x, q0.y, q1.x, q1.y};
#pragma unroll
            for (int i = 0; i < 8; i++) {
                u64t a2 = pack2(As[(ty * 8 + i) * 36 + k]);
#pragma unroll
                for (int j = 0; j < 4; j++) fma2(c2[i][j], a2, b2[j]);
            }
        }
        __syncthreads();
    }

#pragma unroll
    for (int i = 0; i < 8; i++) {
        int r = row0 + ty * 8 + i;
        if (r < M) {
            u64t d2 = pack2(g_dinv[r]);
            size_t off = (size_t)r * 128 + tx * 8;
            ulonglong2 o0, o1;
            o0.x = mul2(c2[i][0], d2); o0.y = mul2(c2[i][1], d2);
            o1.x = mul2(c2[i][2], d2); o1.y = mul2(c2[i][3], d2);
            *(ulonglong2*)(g_hs + off)     = o0;
            *(ulonglong2*)(g_hs + off + 4) = o1;
        }
    }
}

// ---------------- gather: h[r] = relu(dinv[r]*(hs[r] + sum_in hs[src]) + b) ----
__global__ void gather_kernel(const float* __restrict__ bias, int N,
                              const int* __restrict__ batch, int do_pool)
{
    int gid = blockIdx.x * blockDim.x + threadIdx.x;
    int row = gid >> 5;
    if (row >= N) return;
    int lane = gid & 31;

    const float4* hs4 = (const float4*)g_hs;
    int beg = g_off[row];
    int cnt = g_indeg[row];

    float4 a = hs4[(size_t)row * 32 + lane];
    int k = 0;
    for (; k + 2 <= cnt; k += 2) {
        int s0 = g_srcs[beg + k];
        int s1 = g_srcs[beg + k + 1];
        float4 v0 = hs4[(size_t)s0 * 32 + lane];
        float4 v1 = hs4[(size_t)s1 * 32 + lane];
        a.x += v0.x + v1.x; a.y += v0.y + v1.y;
        a.z += v0.z + v1.z; a.w += v0.w + v1.w;
    }
    if (k < cnt) {
        int s0 = g_srcs[beg + k];
        float4 v0 = hs4[(size_t)s0 * 32 + lane];
        a.x += v0.x; a.y += v0.y; a.z += v0.z; a.w += v0.w;
    }

    float dv = g_dinv[row];
    float4 bb = ((const float4*)bias)[lane];
    a.x = fmaxf(fmaf(a.x, dv, bb.x), 0.f);
    a.y = fmaxf(fmaf(a.y, dv, bb.y), 0.f);
    a.z = fmaxf(fmaf(a.z, dv, bb.z), 0.f);
    a.w = fmaxf(fmaf(a.w, dv, bb.w), 0.f);

    if (!do_pool) {
        *(float4*)(g_h + (size_t)row * 128 + lane * 4) = a;
    } else {
        int b = fetch_idx(batch, (size_t)row, g_ba64);
        float* p = g_sum + b * 128 + lane * 4;
        atomicAdd(p + 0, a.x);
        atomicAdd(p + 1, a.y);
        atomicAdd(p + 2, a.z);
        atomicAdd(p + 3, a.w);
        if (lane == 0) atomicAdd(&g_cnt[b], 1.0f);
    }
}

// ---------------- MLP head ------------------------------------------------------
__global__ __launch_bounds__(128)
void head_kernel(const float* __restrict__ meta,
                 const float* __restrict__ Wh1, const float* __restrict__ bh1,
                 const float* __restrict__ Wh2, const float* __restrict__ bh2,
                 float* __restrict__ out)
{
    int b = blockIdx.x;
    int j = threadIdx.x;
    __shared__ float zin[HID + METAD];
    __shared__ float red[128];

    float inv = 1.0f / fmaxf(g_cnt[b], 1.0f);
    zin[j] = g_sum[b * HID + j] * inv;
    if (j < METAD) zin[HID + j] = meta[b * METAD + j];
    __syncthreads();

    float acc = bh1[j];
#pragma unroll
    for (int k = 0; k < HID + METAD; k++)
        acc = fmaf(zin[k], Wh1[k * HID + j], acc);
    red[j] = fmaxf(acc, 0.0f) * Wh2[j];
    __syncthreads();
#pragma unroll
    for (int s = 64; s > 0; s >>= 1) {
        if (j < s) red[j] += red[j + s];
        __syncthreads();
    }
    if (j == 0) out[b] = red[0] + bh2[0];
}

// --------------------------------------------------------------------------------
extern "C" void kernel_launch(void* const* d_in, const int* in_sizes, int n_in,
                              void* d_out, int out_size)
{
    const float* x     = (const float*)d_in[0];
    const int*   ei    = (const int*)d_in[1];
    const int*   batch = (const int*)d_in[2];
    const float* meta  = (const float*)d_in[3];
    const float* W1 = (const float*)d_in[4];  const float* b1 = (const float*)d_in[5];
    const float* W2 = (const float*)d_in[6];  const float* b2 = (const float*)d_in[7];
    const float* W3 = (const float*)d_in[8];  const float* b3 = (const float*)d_in[9];
    const float* Wh1 = (const float*)d_in[10]; const float* bh1 = (const float*)d_in[11];
    const float* Wh2 = (const float*)d_in[12]; const float* bh2 = (const float*)d_in[13];
    float* out = (float*)d_out;

    int N = in_sizes[0] / HID;
    int E = in_sizes[1] / 2;
    int B = in_sizes[3] / METAD;

    int initN = (N > B * HID) ? N : B * HID;
    init_kernel<<<(initN + 255) / 256, 256>>>(ei, batch, E, N, B);
    hist_kernel<<<(E + 255) / 256, 256>>>(ei, E);

    int nscan = (N + 255) / 256;
    scan_block_kernel<<<nscan, 256>>>(N);
    scan_add_kernel  <<<nscan, 256>>>(N);
    fill_kernel      <<<(E + 255) / 256, 256>>>(ei, E);

    int gblocks = (N + 127) / 128;
    int wblocks = (int)(((long long)N * 32 + 255) / 256);

    gemm_kernel  <<<gblocks, 256>>>(x, W1, N, 0);
    gather_kernel<<<wblocks, 256>>>(b1, N, batch, 0);
    gemm_kernel  <<<gblocks, 256>>>(nullptr, W2, N, 1);
    gather_kernel<<<wblocks, 256>>>(b2, N, batch, 0);
    gemm_kernel  <<<gblocks, 256>>>(nullptr, W3, N, 1);
    gather_kernel<<<wblocks, 256>>>(b3, N, batch, 1);

    head_kernel<<<B, 128>>>(meta, Wh1, bh1, Wh2, bh2, out);
}

// round 7
// speedup vs baseline: 3.2081x; 1.0693x over previous
#include <cuda_runtime.h>
#include <cuda_fp16.h>

#define HID   128
#define NMAX  50000
#define EMAX  600000
#define BMAX  512
#define METAD 27

typedef unsigned long long u64t;

// ---------------- scratch (device globals; no allocation allowed) -------------
__device__ float   g_dinv[NMAX];
__device__ __half2 g_hsh[(size_t)NMAX * 64];   // hs in fp16 (message matrix)
__device__ float   g_h  [(size_t)NMAX * HID];
__device__ float   g_sum[BMAX * HID];
__device__ float   g_cnt[BMAX];
__device__ int     g_indeg[NMAX];
__device__ int     g_off  [NMAX];
__device__ int     g_cur  [NMAX];
__device__ int     g_bsum [256];
__device__ int     g_srcs [EMAX];
__device__ int     g_ei64;
__device__ int     g_ba64;

__device__ __forceinline__ int fetch_idx(const int* __restrict__ p, size_t i, int is64) {
    return is64 ? p[2 * i] : p[i];
}

// ---------------- f32x2 packed helpers ----------------------------------------
__device__ __forceinline__ u64t pack2(float v) {
    u64t r;
    asm("mov.b64 %0, {%1, %1};" : "=l"(r) : "r"(__float_as_uint(v)));
    return r;
}
__device__ __forceinline__ void fma2(u64t& c, u64t a, u64t b) {
    asm("fma.rn.f32x2 %0, %1, %2, %0;" : "+l"(c) : "l"(a), "l"(b));
}
__device__ __forceinline__ u64t mul2(u64t a, u64t b) {
    u64t r;
    asm("mul.rn.f32x2 %0, %1, %2;" : "=l"(r) : "l"(a), "l"(b));
    return r;
}
__device__ __forceinline__ float2 u2f(u64t v) {
    float2 f;
    asm("mov.b64 {%0, %1}, %2;" : "=f"(f.x), "=f"(f.y) : "l"(v));
    return f;
}

// ---------------- init (+ dtype detect on thread 0 of block 0) ----------------
__global__ void init_kernel(const int* __restrict__ ei, const int* __restrict__ batch,
                            int E, int N, int B) {
    int i = blockIdx.x * blockDim.x + threadIdx.x;
    if (i == 0) {
        int all_zero = 1;
        for (int k = 0; k < 48; k++) {
            size_t j = (size_t)(((long long)(k + 1) * (E - 2)) / 49);
            if (ei[2 * j + 1] != 0) { all_zero = 0; break; }
        }
        g_ei64 = all_zero;
        all_zero = 1;
        for (int k = 0; k < 48; k++) {
            size_t j = (size_t)(N / 2 + ((long long)k * (N / 2 - 2)) / 48);
            if (batch[2 * (j / 2) + 1] != 0) { all_zero = 0; break; }
        }
        g_ba64 = all_zero;
    }
    if (i < N) { g_indeg[i] = 0; g_cur[i] = 0; }
    if (i < B * HID) g_sum[i] = 0.0f;
    if (i < B) g_cnt[i] = 0.0f;
}

// ---------------- in-degree histogram ------------------------------------------
__global__ void hist_kernel(const int* __restrict__ ei, int E) {
    int e = blockIdx.x * blockDim.x + threadIdx.x;
    if (e < E) atomicAdd(&g_indeg[fetch_idx(ei, (size_t)E + e, g_ei64)], 1);
}

// ---------------- scan phase 1: per-block exclusive scan ----------------------
__global__ void scan_block_kernel(int N) {
    __shared__ int sh[256];
    int i = blockIdx.x * 256 + threadIdx.x;
    int v = (i < N) ? g_indeg[i] : 0;
    sh[threadIdx.x] = v;
    __syncthreads();
#pragma unroll
    for (int s = 1; s < 256; s <<= 1) {
        int t = (threadIdx.x >= s) ? sh[threadIdx.x - s] : 0;
        __syncthreads();
        sh[threadIdx.x] += t;
        __syncthreads();
    }
    if (i < N) g_off[i] = sh[threadIdx.x] - v;
    if (threadIdx.x == 255) g_bsum[blockIdx.x] = sh[255];
}

// ---------------- scan phase 2: add block-prefix + dinv ------------------------
__global__ void scan_add_kernel(int N) {
    __shared__ int base_sh;
    if (threadIdx.x < 32) {
        int run = 0;
        for (int b = threadIdx.x; b < blockIdx.x; b += 32) run += g_bsum[b];
#pragma unroll
        for (int s = 16; s > 0; s >>= 1) run += __shfl_down_sync(0xffffffffu, run, s);
        if (threadIdx.x == 0) base_sh = run;
    }
    __syncthreads();
    int i = blockIdx.x * 256 + threadIdx.x;
    if (i < N) {
        g_off[i] += base_sh;
        g_dinv[i] = rsqrtf((float)(g_indeg[i] + 1));
    }
}

// ---------------- fill: srcs sorted by dst --------------------------------------
__global__ void fill_kernel(const int* __restrict__ ei, int E) {
    int e = blockIdx.x * blockDim.x + threadIdx.x;
    if (e >= E) return;
    int is64 = g_ei64;
    int s = fetch_idx(ei, (size_t)e, is64);
    int d = fetch_idx(ei, (size_t)E + e, is64);
    int pos = g_off[d] + atomicAdd(&g_cur[d], 1);
    g_srcs[pos] = s;
}

// ---------------- GEMM: hs(fp16) = dinv[row] * (A @ W) -------------------------
// 128x128 tile, 256 threads, 8x8 microtile as 8x4 f32x2 (FFMA2), 2 blocks/SM.
__global__ __launch_bounds__(256, 2)
void gemm_kernel(const float* __restrict__ Aext, const float* __restrict__ W,
                 int M, int use_gh)
{
    __shared__ __align__(16) float As[128 * 36];
    __shared__ __align__(16) float Ws[32 * 128];

    const float* A = use_gh ? g_h : Aext;
    int tid = threadIdx.x;
    int tx = tid & 15;
    int ty = tid >> 4;
    int row0 = blockIdx.x * 128;
    bool full = (row0 + 128 <= M);

    u64t c2[8][4];
#pragma unroll
    for (int i = 0; i < 8; i++)
#pragma unroll
        for (int j = 0; j < 4; j++) c2[i][j] = 0ull;

    for (int kk = 0; kk < 128; kk += 32) {
        {
            const float4* W4 = (const float4*)(W + (size_t)kk * 128);
            float4* Ws4 = (float4*)Ws;
#pragma unroll
            for (int i = 0; i < 4; i++) Ws4[i * 256 + tid] = W4[i * 256 + tid];
        }
#pragma unroll
        for (int i = 0; i < 4; i++) {
            int li = i * 256 + tid;
            int m  = li >> 3;
            int k  = (li & 7) << 2;
            float4 v;
            if (full || (row0 + m) < M)
                v = *(const float4*)(A + (size_t)(row0 + m) * 128 + kk + k);
            else
                v = make_float4(0.f, 0.f, 0.f, 0.f);
            *(float4*)(As + m * 36 + k) = v;
        }
        __syncthreads();

#pragma unroll
        for (int k = 0; k < 32; k++) {
            ulonglong2 q0 = *(const ulonglong2*)(Ws + k * 128 + tx * 8);
            ulonglong2 q1 = *(const ulonglong2*)(Ws + k * 128 + tx * 8 + 4);
            u64t b2[4] = {q0.x, q0.y, q1.x, q1.y};
#pragma unroll
            for (int i = 0; i < 8; i++) {
                u64t a2 = pack2(As[(ty * 8 + i) * 36 + k]);
#pragma unroll
                for (int j = 0; j < 4; j++) fma2(c2[i][j], a2, b2[j]);
            }
        }
        __syncthreads();
    }

#pragma unroll
    for (int i = 0; i < 8; i++) {
        int r = row0 + ty * 8 + i;
        if (r < M) {
            u64t d2 = pack2(g_dinv[r]);
            __half2 o[4];
#pragma unroll
            for (int j = 0; j < 4; j++) {
                float2 f = u2f(mul2(c2[i][j], d2));
                o[j] = __floats2half2_rn(f.x, f.y);
            }
            // 8 halves = 16B per thread; cols tx*8..tx*8+7 of row r
            *(uint4*)(g_hsh + (size_t)r * 64 + tx * 4) = *(const uint4*)o;
        }
    }
}

// ---------------- gather: h[r] = relu(dinv[r]*(hs[r] + sum_in hs[src]) + b) ----
// one warp per row; hs is fp16, accumulation fp32; fused pool on layer 3.
__global__ void gather_kernel(const float* __restrict__ bias, int N,
                              const int* __restrict__ batch, int do_pool)
{
    int gid = blockIdx.x * blockDim.x + threadIdx.x;
    int row = gid >> 5;
    if (row >= N) return;
    int lane = gid & 31;

    const uint2* hs2 = (const uint2*)g_hsh;    // 4 halves per uint2; 32 per row
    int beg = g_off[row];
    int cnt = g_indeg[row];

    float4 a = make_float4(0.f, 0.f, 0.f, 0.f);
    float4 a1 = make_float4(0.f, 0.f, 0.f, 0.f);
#define ACC(dst, rw) do {                                            \
        uint2 _r = hs2[(size_t)(rw) * 32 + lane];                     \
        float2 _lo = __half22float2(*(const __half2*)&_r.x);          \
        float2 _hi = __half22float2(*(const __half2*)&_r.y);          \
        dst.x += _lo.x; dst.y += _lo.y; dst.z += _hi.x; dst.w += _hi.y; \
    } while (0)

    ACC(a, row);                                // self-loop term
    int k = 0;
    for (; k + 4 <= cnt; k += 4) {
        int s0 = g_srcs[beg + k];
        int s1 = g_srcs[beg + k + 1];
        int s2 = g_srcs[beg + k + 2];
        int s3 = g_srcs[beg + k + 3];
        ACC(a, s0); ACC(a1, s1); ACC(a, s2); ACC(a1, s3);
    }
    for (; k < cnt; k++) ACC(a, g_srcs[beg + k]);
    a.x += a1.x; a.y += a1.y; a.z += a1.z; a.w += a1.w;
#undef ACC

    float dv = g_dinv[row];
    float4 bb = ((const float4*)bias)[lane];
    a.x = fmaxf(fmaf(a.x, dv, bb.x), 0.f);
    a.y = fmaxf(fmaf(a.y, dv, bb.y), 0.f);
    a.z = fmaxf(fmaf(a.z, dv, bb.z), 0.f);
    a.w = fmaxf(fmaf(a.w, dv, bb.w), 0.f);

    if (!do_pool) {
        *(float4*)(g_h + (size_t)row * 128 + lane * 4) = a;
    } else {
        int b = fetch_idx(batch, (size_t)row, g_ba64);
        float* p = g_sum + b * 128 + lane * 4;
        atomicAdd(p + 0, a.x);
        atomicAdd(p + 1, a.y);
        atomicAdd(p + 2, a.z);
        atomicAdd(p + 3, a.w);
        if (lane == 0) atomicAdd(&g_cnt[b], 1.0f);
    }
}

// ---------------- MLP head ------------------------------------------------------
__global__ __launch_bounds__(128)
void head_kernel(const float* __restrict__ meta,
                 const float* __restrict__ Wh1, const float* __restrict__ bh1,
                 const float* __restrict__ Wh2, const float* __restrict__ bh2,
                 float* __restrict__ out)
{
    int b = blockIdx.x;
    int j = threadIdx.x;
    __shared__ float zin[HID + METAD];
    __shared__ float red[128];

    float inv = 1.0f / fmaxf(g_cnt[b], 1.0f);
    zin[j] = g_sum[b * HID + j] * inv;
    if (j < METAD) zin[HID + j] = meta[b * METAD + j];
    __syncthreads();

    float acc = bh1[j];
#pragma unroll
    for (int k = 0; k < HID + METAD; k++)
        acc = fmaf(zin[k], Wh1[k * HID + j], acc);
    red[j] = fmaxf(acc, 0.0f) * Wh2[j];
    __syncthreads();
#pragma unroll
    for (int s = 64; s > 0; s >>= 1) {
        if (j < s) red[j] += red[j + s];
        __syncthreads();
    }
    if (j == 0) out[b] = red[0] + bh2[0];
}

// --------------------------------------------------------------------------------
extern "C" void kernel_launch(void* const* d_in, const int* in_sizes, int n_in,
                              void* d_out, int out_size)
{
    const float* x     = (const float*)d_in[0];
    const int*   ei    = (const int*)d_in[1];
    const int*   batch = (const int*)d_in[2];
    const float* meta  = (const float*)d_in[3];
    const float* W1 = (const float*)d_in[4];  const float* b1 = (const float*)d_in[5];
    const float* W2 = (const float*)d_in[6];  const float* b2 = (const float*)d_in[7];
    const float* W3 = (const float*)d_in[8];  const float* b3 = (const float*)d_in[9];
    const float* Wh1 = (const float*)d_in[10]; const float* bh1 = (const float*)d_in[11];
    const float* Wh2 = (const float*)d_in[12]; const float* bh2 = (const float*)d_in[13];
    float* out = (float*)d_out;

    int N = in_sizes[0] / HID;
    int E = in_sizes[1] / 2;
    int B = in_sizes[3] / METAD;

    int initN = (N > B * HID) ? N : B * HID;
    init_kernel<<<(initN + 255) / 256, 256>>>(ei, batch, E, N, B);
    hist_kernel<<<(E + 255) / 256, 256>>>(ei, E);

    int nscan = (N + 255) / 256;
    scan_block_kernel<<<nscan, 256>>>(N);
    scan_add_kernel  <<<nscan, 256>>>(N);
    fill_kernel      <<<(E + 255) / 256, 256>>>(ei, E);

    int gblocks = (N + 127) / 128;
    int wblocks = (int)(((long long)N * 32 + 255) / 256);

    gemm_kernel  <<<gblocks, 256>>>(x, W1, N, 0);
    gather_kernel<<<wblocks, 256>>>(b1, N, batch, 0);
    gemm_kernel  <<<gblocks, 256>>>(nullptr, W2, N, 1);
    gather_kernel<<<wblocks, 256>>>(b2, N, batch, 0);
    gemm_kernel  <<<gblocks, 256>>>(nullptr, W3, N, 1);
    gather_kernel<<<wblocks, 256>>>(b3, N, batch, 1);

    head_kernel<<<B, 128>>>(meta, Wh1, bh1, Wh2, bh2, out);
}

// round 8
// speedup vs baseline: 3.6001x; 1.1222x over previous
#include <cuda_runtime.h>
#include <cuda_fp16.h>

#define HID   128
#define NMAX  50000
#define EMAX  600000
#define BMAX  512
#define METAD 27

typedef unsigned int       u32;
typedef unsigned long long u64;

// ---------------- scratch (device globals; no allocation allowed) -------------
__device__ float   g_dinv[NMAX];
__device__ __half2 g_hsh[(size_t)NMAX * 64];   // hs messages, fp16
__device__ __half  g_hh [(size_t)NMAX * HID];  // h activations, fp16
__device__ float   g_sum[BMAX * HID];
__device__ float   g_cnt[BMAX];
__device__ int     g_indeg[NMAX];
__device__ int     g_off  [NMAX];
__device__ int     g_cur  [NMAX];
__device__ int     g_bsum [256];
__device__ int     g_srcs [EMAX];
__device__ int     g_ei64;
__device__ int     g_ba64;

__device__ __forceinline__ int fetch_idx(const int* __restrict__ p, size_t i, int is64) {
    return is64 ? p[2 * i] : p[i];
}

// ---------------- init (+ dtype detect on thread 0 of block 0) ----------------
__global__ void init_kernel(const int* __restrict__ ei, const int* __restrict__ batch,
                            int E, int N, int B) {
    int i = blockIdx.x * blockDim.x + threadIdx.x;
    if (i == 0) {
        int all_zero = 1;
        for (int k = 0; k < 48; k++) {
            size_t j = (size_t)(((long long)(k + 1) * (E - 2)) / 49);
            if (ei[2 * j + 1] != 0) { all_zero = 0; break; }
        }
        g_ei64 = all_zero;
        all_zero = 1;
        for (int k = 0; k < 48; k++) {
            size_t j = (size_t)(N / 2 + ((long long)k * (N / 2 - 2)) / 48);
            if (batch[2 * (j / 2) + 1] != 0) { all_zero = 0; break; }
        }
        g_ba64 = all_zero;
    }
    if (i < N) { g_indeg[i] = 0; g_cur[i] = 0; }
    if (i < B * HID) g_sum[i] = 0.0f;
    if (i < B) g_cnt[i] = 0.0f;
}

// ---------------- in-degree histogram ------------------------------------------
__global__ void hist_kernel(const int* __restrict__ ei, int E) {
    int e = blockIdx.x * blockDim.x + threadIdx.x;
    if (e < E) atomicAdd(&g_indeg[fetch_idx(ei, (size_t)E + e, g_ei64)], 1);
}

// ---------------- scan phase 1: per-block exclusive scan ----------------------
__global__ void scan_block_kernel(int N) {
    __shared__ int sh[256];
    int i = blockIdx.x * 256 + threadIdx.x;
    int v = (i < N) ? g_indeg[i] : 0;
    sh[threadIdx.x] = v;
    __syncthreads();
#pragma unroll
    for (int s = 1; s < 256; s <<= 1) {
        int t = (threadIdx.x >= s) ? sh[threadIdx.x - s] : 0;
        __syncthreads();
        sh[threadIdx.x] += t;
        __syncthreads();
    }
    if (i < N) g_off[i] = sh[threadIdx.x] - v;
    if (threadIdx.x == 255) g_bsum[blockIdx.x] = sh[255];
}

// ---------------- scan phase 2: add block-prefix + dinv ------------------------
__global__ void scan_add_kernel(int N) {
    __shared__ int base_sh;
    if (threadIdx.x < 32) {
        int run = 0;
        for (int b = threadIdx.x; b < blockIdx.x; b += 32) run += g_bsum[b];
#pragma unroll
        for (int s = 16; s > 0; s >>= 1) run += __shfl_down_sync(0xffffffffu, run, s);
        if (threadIdx.x == 0) base_sh = run;
    }
    __syncthreads();
    int i = blockIdx.x * 256 + threadIdx.x;
    if (i < N) {
        g_off[i] += base_sh;
        g_dinv[i] = rsqrtf((float)(g_indeg[i] + 1));
    }
}

// ---------------- fill: srcs sorted by dst --------------------------------------
__global__ void fill_kernel(const int* __restrict__ ei, int E) {
    int e = blockIdx.x * blockDim.x + threadIdx.x;
    if (e >= E) return;
    int is64 = g_ei64;
    int s = fetch_idx(ei, (size_t)e, is64);
    int d = fetch_idx(ei, (size_t)E + e, is64);
    int pos = g_off[d] + atomicAdd(&g_cur[d], 1);
    g_srcs[pos] = s;
}

// ---------------- GEMM (fp16 HFMA2): hs(fp16) = dinv[row] * (A @ W) ------------
// 128x128 tile, 256 threads, 8x8 microtile. A pre-splatted half2 pairs in SMEM
// (LDS.64 -> 2 k-steps), B fp16 rows (LDS.128 -> 8 cols). Dual fp16 acc sets
// (even/odd k), merged in fp32 at epilogue.
__global__ __launch_bounds__(256, 2)
void gemm_kernel(const float* __restrict__ Aext, const float* __restrict__ W,
                 int M, int use_gh)
{
    __shared__ __align__(16) u64    As64[128 * 17];   // [m][kpair] pitch 17
    __shared__ __align__(16) __half Bs[32 * 128];     // [k][n]

    int tid = threadIdx.x;
    int tx = tid & 15;
    int ty = tid >> 4;
    int row0 = blockIdx.x * 128;
    bool full = (row0 + 128 <= M);

    __half2 acc[2][8][4];
    __half2 z2 = __floats2half2_rn(0.f, 0.f);
#pragma unroll
    for (int s = 0; s < 2; s++)
#pragma unroll
        for (int i = 0; i < 8; i++)
#pragma unroll
            for (int j = 0; j < 4; j++) acc[s][i][j] = z2;

    for (int kk = 0; kk < 128; kk += 32) {
        // ---- B chunk: rows kk..kk+31 fp32 -> fp16 [k][n]
        {
            const float4* W4 = (const float4*)(W + (size_t)kk * 128);
#pragma unroll
            for (int i = 0; i < 4; i++) {
                int f  = i * 256 + tid;     // 0..1023 float4 slots
                int k  = f >> 5;
                int n4 = f & 31;
                float4 v = W4[f];
                __half2 h0 = __floats2half2_rn(v.x, v.y);
                __half2 h1 = __floats2half2_rn(v.z, v.w);
                uint2 st;
                st.x = *(u32*)&h0; st.y = *(u32*)&h1;
                *(uint2*)(Bs + k * 128 + n4 * 4) = st;
            }
        }
        // ---- A chunk: 128 rows x 32 k -> splatted half2 pairs
#pragma unroll
        for (int i = 0; i < 4; i++) {
            int idx = i * 256 + tid;        // 0..1023 (m, kquad)
            int m   = idx >> 3;
            int q   = idx & 7;
            __half a[4];
            bool inb = full || (row0 + m) < M;
            if (use_gh) {
                if (inb) {
                    uint2 r = *(const uint2*)(g_hh + (size_t)(row0 + m) * HID + kk + q * 4);
                    __half2 p0 = *(__half2*)&r.x;
                    __half2 p1 = *(__half2*)&r.y;
                    a[0] = __low2half(p0); a[1] = __high2half(p0);
                    a[2] = __low2half(p1); a[3] = __high2half(p1);
                } else {
                    a[0] = a[1] = a[2] = a[3] = __float2half(0.f);
                }
            } else {
                float4 v = inb ? *(const float4*)(Aext + (size_t)(row0 + m) * HID + kk + q * 4)
                               : make_float4(0.f, 0.f, 0.f, 0.f);
                a[0] = __float2half_rn(v.x); a[1] = __float2half_rn(v.y);
                a[2] = __float2half_rn(v.z); a[3] = __float2half_rn(v.w);
            }
            __half2 s0 = __half2half2(a[0]), s1 = __half2half2(a[1]);
            __half2 s2 = __half2half2(a[2]), s3 = __half2half2(a[3]);
            u64 w0 = ((u64)(*(u32*)&s1) << 32) | (u64)(*(u32*)&s0);
            u64 w1 = ((u64)(*(u32*)&s3) << 32) | (u64)(*(u32*)&s2);
            As64[m * 17 + q * 2]     = w0;
            As64[m * 17 + q * 2 + 1] = w1;
        }
        __syncthreads();

#pragma unroll
        for (int p = 0; p < 16; p++) {       // k-pair
            uint4 b0 = *(const uint4*)(Bs + (2 * p)     * 128 + tx * 8);
            uint4 b1 = *(const uint4*)(Bs + (2 * p + 1) * 128 + tx * 8);
            __half2 be[4] = {*(__half2*)&b0.x, *(__half2*)&b0.y, *(__half2*)&b0.z, *(__half2*)&b0.w};
            __half2 bo[4] = {*(__half2*)&b1.x, *(__half2*)&b1.y, *(__half2*)&b1.z, *(__half2*)&b1.w};
#pragma unroll
            for (int i = 0; i < 8; i++) {
                u64 av = As64[(ty * 8 + i) * 17 + p];
                u32 lo = (u32)av, hi = (u32)(av >> 32);
                __half2 ae = *(__half2*)&lo;
                __half2 ao = *(__half2*)&hi;
#pragma unroll
                for (int j = 0; j < 4; j++) {
                    acc[0][i][j] = __hfma2(ae, be[j], acc[0][i][j]);
                    acc[1][i][j] = __hfma2(ao, bo[j], acc[1][i][j]);
                }
            }
        }
        __syncthreads();
    }

    // epilogue: merge sets in fp32, scale dinv, write g_hsh fp16
#pragma unroll
    for (int i = 0; i < 8; i++) {
        int r = row0 + ty * 8 + i;
        if (r < M) {
            float dv = g_dinv[r];
            __half2 o[4];
#pragma unroll
            for (int j = 0; j < 4; j++) {
                float2 f0 = __half22float2(acc[0][i][j]);
                float2 f1 = __half22float2(acc[1][i][j]);
                o[j] = __floats2half2_rn((f0.x + f1.x) * dv, (f0.y + f1.y) * dv);
            }
            *(uint4*)(g_hsh + (size_t)r * 64 + tx * 4) = *(const uint4*)o;
        }
    }
}

// ---------------- gather: h[r](fp16) = relu(dinv[r]*(hs[r] + sum hs[src]) + b) -
__global__ void gather_kernel(const float* __restrict__ bias, int N,
                              const int* __restrict__ batch, int do_pool)
{
    int gid = blockIdx.x * blockDim.x + threadIdx.x;
    int row = gid >> 5;
    if (row >= N) return;
    int lane = gid & 31;

    const uint2* hs2 = (const uint2*)g_hsh;    // 4 halves per uint2; 32 per row
    int beg = g_off[row];
    int cnt = g_indeg[row];

    float4 a  = make_float4(0.f, 0.f, 0.f, 0.f);
    float4 a1 = make_float4(0.f, 0.f, 0.f, 0.f);
#define ACC(dst, rw) do {                                             \
        uint2 _r = hs2[(size_t)(rw) * 32 + lane];                      \
        float2 _lo = __half22float2(*(const __half2*)&_r.x);           \
        float2 _hi = __half22float2(*(const __half2*)&_r.y);           \
        dst.x += _lo.x; dst.y += _lo.y; dst.z += _hi.x; dst.w += _hi.y; \
    } while (0)

    ACC(a, row);                                // self-loop term
    int k = 0;
    for (; k + 4 <= cnt; k += 4) {
        int s0 = g_srcs[beg + k];
        int s1 = g_srcs[beg + k + 1];
        int s2 = g_srcs[beg + k + 2];
        int s3 = g_srcs[beg + k + 3];
        ACC(a, s0); ACC(a1, s1); ACC(a, s2); ACC(a1, s3);
    }
    for (; k < cnt; k++) ACC(a, g_srcs[beg + k]);
    a.x += a1.x; a.y += a1.y; a.z += a1.z; a.w += a1.w;
#undef ACC

    float dv = g_dinv[row];
    float4 bb = ((const float4*)bias)[lane];
    a.x = fmaxf(fmaf(a.x, dv, bb.x), 0.f);
    a.y = fmaxf(fmaf(a.y, dv, bb.y), 0.f);
    a.z = fmaxf(fmaf(a.z, dv, bb.z), 0.f);
    a.w = fmaxf(fmaf(a.w, dv, bb.w), 0.f);

    if (!do_pool) {
        __half2 h0 = __floats2half2_rn(a.x, a.y);
        __half2 h1 = __floats2half2_rn(a.z, a.w);
        uint2 st;
        st.x = *(u32*)&h0; st.y = *(u32*)&h1;
        *(uint2*)(g_hh + (size_t)row * HID + lane * 4) = st;
    } else {
        int b = fetch_idx(batch, (size_t)row, g_ba64);
        float* p = g_sum + b * 128 + lane * 4;
        atomicAdd(p + 0, a.x);
        atomicAdd(p + 1, a.y);
        atomicAdd(p + 2, a.z);
        atomicAdd(p + 3, a.w);
        if (lane == 0) atomicAdd(&g_cnt[b], 1.0f);
    }
}

// ---------------- MLP head ------------------------------------------------------
__global__ __launch_bounds__(128)
void head_kernel(const float* __restrict__ meta,
                 const float* __restrict__ Wh1, const float* __restrict__ bh1,
                 const float* __restrict__ Wh2, const float* __restrict__ bh2,
                 float* __restrict__ out)
{
    int b = blockIdx.x;
    int j = threadIdx.x;
    __shared__ float zin[HID + METAD];
    __shared__ float red[128];

    float inv = 1.0f / fmaxf(g_cnt[b], 1.0f);
    zin[j] = g_sum[b * HID + j] * inv;
    if (j < METAD) zin[HID + j] = meta[b * METAD + j];
    __syncthreads();

    float acc = bh1[j];
#pragma unroll
    for (int k = 0; k < HID + METAD; k++)
        acc = fmaf(zin[k], Wh1[k * HID + j], acc);
    red[j] = fmaxf(acc, 0.0f) * Wh2[j];
    __syncthreads();
#pragma unroll
    for (int s = 64; s > 0; s >>= 1) {
        if (j < s) red[j] += red[j + s];
        __syncthreads();
    }
    if (j == 0) out[b] = red[0] + bh2[0];
}

// --------------------------------------------------------------------------------
extern "C" void kernel_launch(void* const* d_in, const int* in_sizes, int n_in,
                              void* d_out, int out_size)
{
    const float* x     = (const float*)d_in[0];
    const int*   ei    = (const int*)d_in[1];
    const int*   batch = (const int*)d_in[2];
    const float* meta  = (const float*)d_in[3];
    const float* W1 = (const float*)d_in[4];  const float* b1 = (const float*)d_in[5];
    const float* W2 = (const float*)d_in[6];  const float* b2 = (const float*)d_in[7];
    const float* W3 = (const float*)d_in[8];  const float* b3 = (const float*)d_in[9];
    const float* Wh1 = (const float*)d_in[10]; const float* bh1 = (const float*)d_in[11];
    const float* Wh2 = (const float*)d_in[12]; const float* bh2 = (const float*)d_in[13];
    float* out = (float*)d_out;

    int N = in_sizes[0] / HID;
    int E = in_sizes[1] / 2;
    int B = in_sizes[3] / METAD;

    int initN = (N > B * HID) ? N : B * HID;
    init_kernel<<<(initN + 255) / 256, 256>>>(ei, batch, E, N, B);
    hist_kernel<<<(E + 255) / 256, 256>>>(ei, E);

    int nscan = (N + 255) / 256;
    scan_block_kernel<<<nscan, 256>>>(N);
    scan_add_kernel  <<<nscan, 256>>>(N);
    fill_kernel      <<<(E + 255) / 256, 256>>>(ei, E);

    int gblocks = (N + 127) / 128;
    int wblocks = (int)(((long long)N * 32 + 255) / 256);

    gemm_kernel  <<<gblocks, 256>>>(x, W1, N, 0);
    gather_kernel<<<wblocks, 256>>>(b1, N, batch, 0);
    gemm_kernel  <<<gblocks, 256>>>(nullptr, W2, N, 1);
    gather_kernel<<<wblocks, 256>>>(b2, N, batch, 0);
    gemm_kernel  <<<gblocks, 256>>>(nullptr, W3, N, 1);
    gather_kernel<<<wblocks, 256>>>(b3, N, batch, 1);

    head_kernel<<<B, 128>>>(meta, Wh1, bh1, Wh2, bh2, out);
}

// round 10
// speedup vs baseline: 3.6688x; 1.0191x over previous
#include <cuda_runtime.h>
#include <cuda_fp16.h>

#define HID   128
#define NMAX  50000
#define EMAX  600000
#define BMAX  512
#define METAD 27

typedef unsigned int       u32;
typedef unsigned long long u64;

// ---------------- scratch (device globals; no allocation allowed) -------------
__device__ float   g_dinv[NMAX];
__device__ __half2 g_hsh[(size_t)NMAX * 64];   // hs messages, fp16
__device__ __half  g_hh [(size_t)NMAX * HID];  // h activations, fp16
__device__ float   g_sum[BMAX * HID];
__device__ float   g_cnt[BMAX];
__device__ int     g_indeg[NMAX];
__device__ int     g_off  [NMAX];
__device__ int     g_cur  [NMAX];
__device__ int     g_bsum [256];
__device__ int     g_srcs [EMAX];
__device__ int     g_ei64;
__device__ int     g_ba64;

__device__ __forceinline__ int fetch_idx(const int* __restrict__ p, size_t i, int is64) {
    return is64 ? p[2 * i] : p[i];
}

// ---------------- init (+ dtype detect on thread 0 of block 0) ----------------
__global__ void init_kernel(const int* __restrict__ ei, const int* __restrict__ batch,
                            int E, int N, int B) {
    int i = blockIdx.x * blockDim.x + threadIdx.x;
    if (i == 0) {
        int all_zero = 1;
        for (int k = 0; k < 48; k++) {
            size_t j = (size_t)(((long long)(k + 1) * (E - 2)) / 49);
            if (ei[2 * j + 1] != 0) { all_zero = 0; break; }
        }
        g_ei64 = all_zero;
        all_zero = 1;
        for (int k = 0; k < 48; k++) {
            size_t j = (size_t)(N / 2 + ((long long)k * (N / 2 - 2)) / 48);
            if (batch[2 * (j / 2) + 1] != 0) { all_zero = 0; break; }
        }
        g_ba64 = all_zero;
    }
    if (i < N) { g_indeg[i] = 0; g_cur[i] = 0; }
    if (i < B * HID) g_sum[i] = 0.0f;
    if (i < B) g_cnt[i] = 0.0f;
}

// ---------------- in-degree histogram ------------------------------------------
__global__ void hist_kernel(const int* __restrict__ ei, int E) {
    int e = blockIdx.x * blockDim.x + threadIdx.x;
    if (e < E) atomicAdd(&g_indeg[fetch_idx(ei, (size_t)E + e, g_ei64)], 1);
}

// ---------------- scan phase 1: per-block exclusive scan ----------------------
__global__ void scan_block_kernel(int N) {
    __shared__ int sh[256];
    int i = blockIdx.x * 256 + threadIdx.x;
    int v = (i < N) ? g_indeg[i] : 0;
    sh[threadIdx.x] = v;
    __syncthreads();
#pragma unroll
    for (int s = 1; s < 256; s <<= 1) {
        int t = (threadIdx.x >= s) ? sh[threadIdx.x - s] : 0;
        __syncthreads();
        sh[threadIdx.x] += t;
        __syncthreads();
    }
    if (i < N) g_off[i] = sh[threadIdx.x] - v;
    if (threadIdx.x == 255) g_bsum[blockIdx.x] = sh[255];
}

// ---------------- scan phase 2: add block-prefix + dinv ------------------------
__global__ void scan_add_kernel(int N) {
    __shared__ int base_sh;
    if (threadIdx.x < 32) {
        int run = 0;
        for (int b = threadIdx.x; b < blockIdx.x; b += 32) run += g_bsum[b];
#pragma unroll
        for (int s = 16; s > 0; s >>= 1) run += __shfl_down_sync(0xffffffffu, run, s);
        if (threadIdx.x == 0) base_sh = run;
    }
    __syncthreads();
    int i = blockIdx.x * 256 + threadIdx.x;
    if (i < N) {
        g_off[i] += base_sh;
        g_dinv[i] = rsqrtf((float)(g_indeg[i] + 1));
    }
}

// ---------------- fill: srcs sorted by dst --------------------------------------
__global__ void fill_kernel(const int* __restrict__ ei, int E) {
    int e = blockIdx.x * blockDim.x + threadIdx.x;
    if (e >= E) return;
    int is64 = g_ei64;
    int s = fetch_idx(ei, (size_t)e, is64);
    int d = fetch_idx(ei, (size_t)E + e, is64);
    int pos = g_off[d] + atomicAdd(&g_cur[d], 1);
    g_srcs[pos] = s;
}

// ---------------- GEMM (fp16 HFMA2): hs(fp16) = dinv[row] * (A @ W) ------------
// 128x128 tile, 256 threads. A resident in SMEM for the whole K (filled once);
// B in two 64-k chunks. 3 barriers per block total. Dual fp16 acc sets, merged
// in fp32 with the dinv scale at epilogue.
__global__ __launch_bounds__(256, 2)
void gemm_kernel(const float* __restrict__ Aext, const float* __restrict__ W,
                 int M, int use_gh)
{
    __shared__ __align__(16) __half As[128 * 128];   // [m][k]
    __shared__ __align__(16) __half Bs[64 * 128];    // [k_local][n]

    int tid = threadIdx.x;
    int tx = tid & 15;
    int ty = tid >> 4;
    int row0 = blockIdx.x * 128;
    bool full = (row0 + 128 <= M);

    // ---- fill A (once, full K) ----
    if (use_gh) {
        // 2048 uint4 slots = 128 rows x 16 uint4 (8 halves each)
#pragma unroll
        for (int i = 0; i < 8; i++) {
            int idx = i * 256 + tid;
            int m   = idx >> 4;             // 0..127
            int k8  = idx & 15;             // 0..15
            uint4 v;
            if (full || (row0 + m) < M)
                v = *(const uint4*)(g_hh + (size_t)(row0 + m) * HID + k8 * 8);
            else
                v = make_uint4(0, 0, 0, 0);
            *(uint4*)(As + m * 128 + k8 * 8) = v;
        }
    } else {
#pragma unroll
        for (int i = 0; i < 16; i++) {
            int idx = i * 256 + tid;        // 4096 float4 slots
            int m   = idx >> 5;
            int k4  = idx & 31;
            float4 v;
            if (full || (row0 + m) < M)
                v = *(const float4*)(Aext + (size_t)(row0 + m) * HID + k4 * 4);
            else
                v = make_float4(0.f, 0.f, 0.f, 0.f);
            __half2 h0 = __floats2half2_rn(v.x, v.y);
            __half2 h1 = __floats2half2_rn(v.z, v.w);
            uint2 st; st.x = *(u32*)&h0; st.y = *(u32*)&h1;
            *(uint2*)(As + m * 128 + k4 * 4) = st;
        }
    }

    __half2 acc[2][8][4];
    __half2 z2 = __floats2half2_rn(0.f, 0.f);
#pragma unroll
    for (int s = 0; s < 2; s++)
#pragma unroll
        for (int i = 0; i < 8; i++)
#pragma unroll
            for (int j = 0; j < 4; j++) acc[s][i][j] = z2;

#pragma unroll
    for (int c = 0; c < 2; c++) {
        int k0 = c * 64;
        // ---- fill B chunk: W rows k0..k0+63, fp32 -> fp16 [k_local][n] ----
#pragma unroll
        for (int i = 0; i < 8; i++) {
            int f  = i * 256 + tid;         // 2048 float4 slots
            int k  = f >> 5;
            int n4 = f & 31;
            float4 v = *(const float4*)(W + (size_t)(k0 + k) * 128 + n4 * 4);
            __half2 h0 = __floats2half2_rn(v.x, v.y);
            __half2 h1 = __floats2half2_rn(v.z, v.w);
            uint2 st; st.x = *(u32*)&h0; st.y = *(u32*)&h1;
            *(uint2*)(Bs + k * 128 + n4 * 4) = st;
        }
        __syncthreads();

#pragma unroll
        for (int p = 0; p < 32; p++) {      // local k-pair
            uint4 b0 = *(const uint4*)(Bs + (2 * p)     * 128 + tx * 8);
            uint4 b1 = *(const uint4*)(Bs + (2 * p + 1) * 128 + tx * 8);
            __half2 be[4] = {*(__half2*)&b0.x, *(__half2*)&b0.y, *(__half2*)&b0.z, *(__half2*)&b0.w};
            __half2 bo[4] = {*(__half2*)&b1.x, *(__half2*)&b1.y, *(__half2*)&b1.z, *(__half2*)&b1.w};
#pragma unroll
            for (int i = 0; i < 8; i++) {
                __half2 a2 = *(const __half2*)(As + (ty * 8 + i) * 128 + k0 + 2 * p);
                __half2 ae = __half2half2(__low2half(a2));
                __half2 ao = __half2half2(__high2half(a2));
#pragma unroll
                for (int j = 0; j < 4; j++) {
                    acc[0][i][j] = __hfma2(ae, be[j], acc[0][i][j]);
                    acc[1][i][j] = __hfma2(ao, bo[j], acc[1][i][j]);
                }
            }
        }
        if (c == 0) __syncthreads();        // Bs reused by chunk 1
    }

    // ---- epilogue: merge sets in fp32, scale dinv, write g_hsh fp16 ----
#pragma unroll
    for (int i = 0; i < 8; i++) {
        int r = row0 + ty * 8 + i;
        if (r < M) {
            float dv = g_dinv[r];
            __half2 o[4];
#pragma unroll
            for (int j = 0; j < 4; j++) {
                float2 f0 = __half22float2(acc[0][i][j]);
                float2 f1 = __half22float2(acc[1][i][j]);
                o[j] = __floats2half2_rn((f0.x + f1.x) * dv, (f0.y + f1.y) * dv);
            }
            *(uint4*)(g_hsh + (size_t)r * 64 + tx * 4) = *(const uint4*)o;
        }
    }
}

// ---------------- gather: h[r](fp16) = relu(dinv[r]*(hs[r] + sum hs[src]) + b) -
__global__ void gather_kernel(const float* __restrict__ bias, int N,
                              const int* __restrict__ batch, int do_pool)
{
    int gid = blockIdx.x * blockDim.x + threadIdx.x;
    int row = gid >> 5;
    if (row >= N) return;
    int lane = gid & 31;

    const uint2* hs2 = (const uint2*)g_hsh;
    int beg = g_off[row];
    int cnt = g_indeg[row];

    float4 a  = make_float4(0.f, 0.f, 0.f, 0.f);
    float4 a1 = make_float4(0.f, 0.f, 0.f, 0.f);
#define ACC(dst, rw) do {                                             \
        uint2 _r = hs2[(size_t)(rw) * 32 + lane];                      \
        float2 _lo = __half22float2(*(const __half2*)&_r.x);           \
        float2 _hi = __half22float2(*(const __half2*)&_r.y);           \
        dst.x += _lo.x; dst.y += _lo.y; dst.z += _hi.x; dst.w += _hi.y; \
    } while (0)

    ACC(a, row);
    int k = 0;
    for (; k + 4 <= cnt; k += 4) {
        int s0 = g_srcs[beg + k];
        int s1 = g_srcs[beg + k + 1];
        int s2 = g_srcs[beg + k + 2];
        int s3 = g_srcs[beg + k + 3];
        ACC(a, s0); ACC(a1, s1); ACC(a, s2); ACC(a1, s3);
    }
    for (; k < cnt; k++) ACC(a, g_srcs[beg + k]);
    a.x += a1.x; a.y += a1.y; a.z += a1.z; a.w += a1.w;
#undef ACC

    float dv = g_dinv[row];
    float4 bb = ((const float4*)bias)[lane];
    a.x = fmaxf(fmaf(a.x, dv, bb.x), 0.f);
    a.y = fmaxf(fmaf(a.y, dv, bb.y), 0.f);
    a.z = fmaxf(fmaf(a.z, dv, bb.z), 0.f);
    a.w = fmaxf(fmaf(a.w, dv, bb.w), 0.f);

    if (!do_pool) {
        __half2 h0 = __floats2half2_rn(a.x, a.y);
        __half2 h1 = __floats2half2_rn(a.z, a.w);
        uint2 st; st.x = *(u32*)&h0; st.y = *(u32*)&h1;
        *(uint2*)(g_hh + (size_t)row * HID + lane * 4) = st;
    } else {
        int b = fetch_idx(batch, (size_t)row, g_ba64);
        float* p = g_sum + b * 128 + lane * 4;
        atomicAdd(p + 0, a.x);
        atomicAdd(p + 1, a.y);
        atomicAdd(p + 2, a.z);
        atomicAdd(p + 3, a.w);
        if (lane == 0) atomicAdd(&g_cnt[b], 1.0f);
    }
}

// ---------------- MLP head ------------------------------------------------------
__global__ __launch_bounds__(128)
void head_kernel(const float* __restrict__ meta,
                 const float* __restrict__ Wh1, const float* __restrict__ bh1,
                 const float* __restrict__ Wh2, const float* __restrict__ bh2,
                 float* __restrict__ out)
{
    int b = blockIdx.x;
    int j = threadIdx.x;
    __shared__ float zin[HID + METAD];
    __shared__ float red[128];

    float inv = 1.0f / fmaxf(g_cnt[b], 1.0f);
    zin[j] = g_sum[b * HID + j] * inv;
    if (j < METAD) zin[HID + j] = meta[b * METAD + j];
    __syncthreads();

    float acc = bh1[j];
#pragma unroll
    for (int k = 0; k < HID + METAD; k++)
        acc = fmaf(zin[k], Wh1[k * HID + j], acc);
    red[j] = fmaxf(acc, 0.0f) * Wh2[j];
    __syncthreads();
#pragma unroll
    for (int s = 64; s > 0; s >>= 1) {
        if (j < s) red[j] += red[j + s];
        __syncthreads();
    }
    if (j == 0) out[b] = red[0] + bh2[0];
}

// --------------------------------------------------------------------------------
extern "C" void kernel_launch(void* const* d_in, const int* in_sizes, int n_in,
                              void* d_out, int out_size)
{
    const float* x     = (const float*)d_in[0];
    const int*   ei    = (const int*)d_in[1];
    const int*   batch = (const int*)d_in[2];
    const float* meta  = (const float*)d_in[3];
    const float* W1 = (const float*)d_in[4];  const float* b1 = (const float*)d_in[5];
    const float* W2 = (const float*)d_in[6];  const float* b2 = (const float*)d_in[7];
    const float* W3 = (const float*)d_in[8];  const float* b3 = (const float*)d_in[9];
    const float* Wh1 = (const float*)d_in[10]; const float* bh1 = (const float*)d_in[11];
    const float* Wh2 = (const float*)d_in[12]; const float* bh2 = (const float*)d_in[13];
    float* out = (float*)d_out;

    int N = in_sizes[0] / HID;
    int E = in_sizes[1] / 2;
    int B = in_sizes[3] / METAD;

    int initN = (N > B * HID) ? N : B * HID;
    init_kernel<<<(initN + 255) / 256, 256>>>(ei, batch, E, N, B);
    hist_kernel<<<(E + 255) / 256, 256>>>(ei, E);

    int nscan = (N + 255) / 256;
    scan_block_kernel<<<nscan, 256>>>(N);
    scan_add_kernel  <<<nscan, 256>>>(N);
    fill_kernel      <<<(E + 255) / 256, 256>>>(ei, E);

    int gblocks = (N + 127) / 128;
    int wblocks = (int)(((long long)N * 32 + 255) / 256);

    gemm_kernel  <<<gblocks, 256>>>(x, W1, N, 0);
    gather_kernel<<<wblocks, 256>>>(b1, N, batch, 0);
    gemm_kernel  <<<gblocks, 256>>>(nullptr, W2, N, 1);
    gather_kernel<<<wblocks, 256>>>(b2, N, batch, 0);
    gemm_kernel  <<<gblocks, 256>>>(nullptr, W3, N, 1);
    gather_kernel<<<wblocks, 256>>>(b3, N, batch, 1);

    head_kernel<<<B, 128>>>(meta, Wh1, bh1, Wh2, bh2, out);
}

// round 11
// speedup vs baseline: 5.0775x; 1.3840x over previous
#include <cuda_runtime.h>
#include <cuda_fp16.h>

#define HID   128
#define NMAX  50000
#define EMAX  600000
#define BMAX  512
#define METAD 27

typedef unsigned int       u32;
typedef unsigned long long u64;

// ---------------- scratch (device globals; no allocation allowed) -------------
__device__ float   g_dinv[NMAX];
__device__ __half2 g_hsh[(size_t)NMAX * 64];   // hs messages, fp16
__device__ __half  g_hh [(size_t)NMAX * HID];  // h activations, fp16
__device__ float   g_sum[BMAX * HID];
__device__ float   g_cnt[BMAX];
__device__ int     g_indeg[NMAX];
__device__ int     g_off  [NMAX];
__device__ int     g_cur  [NMAX];
__device__ int     g_bsum [256];
__device__ int     g_srcs [EMAX];
__device__ int     g_ei64;
__device__ int     g_ba64;

__device__ __forceinline__ int fetch_idx(const int* __restrict__ p, size_t i, int is64) {
    return is64 ? p[2 * i] : p[i];
}

__device__ __forceinline__ u32 smem_addr(const void* p) {
    u32 a;
    asm("{ .reg .u64 t; cvta.to.shared.u64 t, %1; cvt.u32.u64 %0, t; }" : "=r"(a) : "l"(p));
    return a;
}
__device__ __forceinline__ void ldsm4(u32* r, u32 addr) {
    asm volatile("ldmatrix.sync.aligned.m8n8.x4.shared.b16 {%0,%1,%2,%3}, [%4];"
        : "=r"(r[0]), "=r"(r[1]), "=r"(r[2]), "=r"(r[3]) : "r"(addr));
}
__device__ __forceinline__ void ldsm4t(u32* r, u32 addr) {
    asm volatile("ldmatrix.sync.aligned.m8n8.x4.trans.shared.b16 {%0,%1,%2,%3}, [%4];"
        : "=r"(r[0]), "=r"(r[1]), "=r"(r[2]), "=r"(r[3]) : "r"(addr));
}
__device__ __forceinline__ void mma16816(float* d, const u32* a, u32 b0, u32 b1) {
    asm volatile("mma.sync.aligned.m16n8k16.row.col.f32.f16.f16.f32 "
        "{%0,%1,%2,%3}, {%4,%5,%6,%7}, {%8,%9}, {%0,%1,%2,%3};"
        : "+f"(d[0]), "+f"(d[1]), "+f"(d[2]), "+f"(d[3])
        : "r"(a[0]), "r"(a[1]), "r"(a[2]), "r"(a[3]), "r"(b0), "r"(b1));
}

// ---------------- init (+ dtype detect on thread 0 of block 0) ----------------
__global__ void init_kernel(const int* __restrict__ ei, const int* __restrict__ batch,
                            int E, int N, int B) {
    int i = blockIdx.x * blockDim.x + threadIdx.x;
    if (i == 0) {
        int all_zero = 1;
        for (int k = 0; k < 48; k++) {
            size_t j = (size_t)(((long long)(k + 1) * (E - 2)) / 49);
            if (ei[2 * j + 1] != 0) { all_zero = 0; break; }
        }
        g_ei64 = all_zero;
        all_zero = 1;
        for (int k = 0; k < 48; k++) {
            size_t j = (size_t)(N / 2 + ((long long)k * (N / 2 - 2)) / 48);
            if (batch[2 * (j / 2) + 1] != 0) { all_zero = 0; break; }
        }
        g_ba64 = all_zero;
    }
    if (i < N) { g_indeg[i] = 0; g_cur[i] = 0; }
    if (i < B * HID) g_sum[i] = 0.0f;
    if (i < B) g_cnt[i] = 0.0f;
}

// ---------------- in-degree histogram ------------------------------------------
__global__ void hist_kernel(const int* __restrict__ ei, int E) {
    int e = blockIdx.x * blockDim.x + threadIdx.x;
    if (e < E) atomicAdd(&g_indeg[fetch_idx(ei, (size_t)E + e, g_ei64)], 1);
}

// ---------------- scan phase 1: per-block exclusive scan ----------------------
__global__ void scan_block_kernel(int N) {
    __shared__ int sh[256];
    int i = blockIdx.x * 256 + threadIdx.x;
    int v = (i < N) ? g_indeg[i] : 0;
    sh[threadIdx.x] = v;
    __syncthreads();
#pragma unroll
    for (int s = 1; s < 256; s <<= 1) {
        int t = (threadIdx.x >= s) ? sh[threadIdx.x - s] : 0;
        __syncthreads();
        sh[threadIdx.x] += t;
        __syncthreads();
    }
    if (i < N) g_off[i] = sh[threadIdx.x] - v;
    if (threadIdx.x == 255) g_bsum[blockIdx.x] = sh[255];
}

// ---------------- scan phase 2: add block-prefix + dinv ------------------------
__global__ void scan_add_kernel(int N) {
    __shared__ int base_sh;
    if (threadIdx.x < 32) {
        int run = 0;
        for (int b = threadIdx.x; b < blockIdx.x; b += 32) run += g_bsum[b];
#pragma unroll
        for (int s = 16; s > 0; s >>= 1) run += __shfl_down_sync(0xffffffffu, run, s);
        if (threadIdx.x == 0) base_sh = run;
    }
    __syncthreads();
    int i = blockIdx.x * 256 + threadIdx.x;
    if (i < N) {
        g_off[i] += base_sh;
        g_dinv[i] = rsqrtf((float)(g_indeg[i] + 1));
    }
}

// ---------------- fill: srcs sorted by dst --------------------------------------
__global__ void fill_kernel(const int* __restrict__ ei, int E) {
    int e = blockIdx.x * blockDim.x + threadIdx.x;
    if (e >= E) return;
    int is64 = g_ei64;
    int s = fetch_idx(ei, (size_t)e, is64);
    int d = fetch_idx(ei, (size_t)E + e, is64);
    int pos = g_off[d] + atomicAdd(&g_cur[d], 1);
    g_srcs[pos] = s;
}

// ---------------- GEMM (mma.sync HMMA): hs(fp16) = dinv[row] * (A @ W) ---------
// 128x128 block tile, 8 warps (4x2), warp tile 32x64, fp32 accumulators.
// A,B fully SMEM-resident (pitch 136 halves -> conflict-free ldmatrix).
#define PITCH 136
__global__ __launch_bounds__(256, 2)
void gemm_kernel(const float* __restrict__ Aext, const float* __restrict__ W,
                 int M, int use_gh)
{
    extern __shared__ __align__(16) __half smem[];
    __half* As = smem;                 // [128][PITCH]
    __half* Bs = smem + 128 * PITCH;   // [128][PITCH]

    int tid = threadIdx.x;
    int row0 = blockIdx.x * 128;
    bool full = (row0 + 128 <= M);

    // ---- fill A ----
    if (use_gh) {
#pragma unroll
        for (int i = 0; i < 8; i++) {
            int idx = i * 256 + tid;        // 2048 uint4 slots: 128 rows x 16
            int m   = idx >> 4;
            int k8  = idx & 15;
            uint4 v;
            if (full || (row0 + m) < M)
                v = *(const uint4*)(g_hh + (size_t)(row0 + m) * HID + k8 * 8);
            else
                v = make_uint4(0, 0, 0, 0);
            *(uint4*)(As + m * PITCH + k8 * 8) = v;
        }
    } else {
#pragma unroll
        for (int i = 0; i < 16; i++) {
            int idx = i * 256 + tid;        // 4096 float4 slots: 128 rows x 32
            int m   = idx >> 5;
            int k4  = idx & 31;
            float4 v;
            if (full || (row0 + m) < M)
                v = *(const float4*)(Aext + (size_t)(row0 + m) * HID + k4 * 4);
            else
                v = make_float4(0.f, 0.f, 0.f, 0.f);
            __half2 h0 = __floats2half2_rn(v.x, v.y);
            __half2 h1 = __floats2half2_rn(v.z, v.w);
            uint2 st; st.x = *(u32*)&h0; st.y = *(u32*)&h1;
            *(uint2*)(As + m * PITCH + k4 * 4) = st;
        }
    }
    // ---- fill B: W [k][n] fp32 -> fp16 ----
#pragma unroll
    for (int i = 0; i < 16; i++) {
        int idx = i * 256 + tid;
        int k   = idx >> 5;
        int n4  = idx & 31;
        float4 v = *(const float4*)(W + (size_t)k * 128 + n4 * 4);
        __half2 h0 = __floats2half2_rn(v.x, v.y);
        __half2 h1 = __floats2half2_rn(v.z, v.w);
        uint2 st; st.x = *(u32*)&h0; st.y = *(u32*)&h1;
        *(uint2*)(Bs + k * PITCH + n4 * 4) = st;
    }
    __syncthreads();

    int wid  = tid >> 5;
    int lane = tid & 31;
    int wm = (wid & 3) * 32;     // warp m offset
    int wn = (wid >> 2) * 64;    // warp n offset

    float acc[2][8][4];
#pragma unroll
    for (int mt = 0; mt < 2; mt++)
#pragma unroll
        for (int nt = 0; nt < 8; nt++)
#pragma unroll
            for (int j = 0; j < 4; j++) acc[mt][nt][j] = 0.f;

    // precomputed lane address components
    int a_row_in = lane & 15;            // row within 16
    int a_koff   = (lane >> 4) * 8;      // 0 or 8 halves
    int b_row_in = (lane & 7) + ((lane >> 3) & 1) * 8;
    int b_noff   = (lane >> 4) * 8;

#pragma unroll
    for (int ks = 0; ks < 8; ks++) {
        int k = ks * 16;
        u32 af[2][4], bf[4][4];
#pragma unroll
        for (int mt = 0; mt < 2; mt++) {
            const __half* p = As + (wm + mt * 16 + a_row_in) * PITCH + k + a_koff;
            ldsm4(af[mt], smem_addr(p));
        }
#pragma unroll
        for (int nt2 = 0; nt2 < 4; nt2++) {
            const __half* p = Bs + (k + b_row_in) * PITCH + wn + nt2 * 16 + b_noff;
            ldsm4t(bf[nt2], smem_addr(p));
        }
#pragma unroll
        for (int mt = 0; mt < 2; mt++)
#pragma unroll
            for (int nt = 0; nt < 8; nt++) {
                int g = nt >> 1, h = nt & 1;
                mma16816(acc[mt][nt], af[mt], bf[g][h * 2], bf[g][h * 2 + 1]);
            }
    }

    // ---- epilogue: scale dinv, write fp16 messages ----
    int gr = lane >> 2;      // row-in-8
    int tc = lane & 3;       // col pair
#pragma unroll
    for (int mt = 0; mt < 2; mt++) {
        int ra = row0 + wm + mt * 16 + gr;
        int rb = ra + 8;
        float dva = (ra < M) ? g_dinv[ra] : 0.f;
        float dvb = (rb < M) ? g_dinv[rb] : 0.f;
#pragma unroll
        for (int nt = 0; nt < 8; nt++) {
            int col = wn + nt * 8 + tc * 2;
            if (ra < M)
                g_hsh[(size_t)ra * 64 + (col >> 1)] =
                    __floats2half2_rn(acc[mt][nt][0] * dva, acc[mt][nt][1] * dva);
            if (rb < M)
                g_hsh[(size_t)rb * 64 + (col >> 1)] =
                    __floats2half2_rn(acc[mt][nt][2] * dvb, acc[mt][nt][3] * dvb);
        }
    }
}

// ---------------- gather: h[r](fp16) = relu(dinv[r]*(hs[r] + sum hs[src]) + b) -
__global__ void gather_kernel(const float* __restrict__ bias, int N,
                              const int* __restrict__ batch, int do_pool)
{
    int gid = blockIdx.x * blockDim.x + threadIdx.x;
    int row = gid >> 5;
    if (row >= N) return;
    int lane = gid & 31;

    const uint2* hs2 = (const uint2*)g_hsh;
    int beg = g_off[row];
    int cnt = g_indeg[row];

    float4 a  = make_float4(0.f, 0.f, 0.f, 0.f);
    float4 a1 = make_float4(0.f, 0.f, 0.f, 0.f);
#define ACC(dst, rw) do {                                             \
        uint2 _r = hs2[(size_t)(rw) * 32 + lane];                      \
        float2 _lo = __half22float2(*(const __half2*)&_r.x);           \
        float2 _hi = __half22float2(*(const __half2*)&_r.y);           \
        dst.x += _lo.x; dst.y += _lo.y; dst.z += _hi.x; dst.w += _hi.y; \
    } while (0)

    ACC(a, row);
    int k = 0;
    for (; k + 4 <= cnt; k += 4) {
        int s0 = g_srcs[beg + k];
        int s1 = g_srcs[beg + k + 1];
        int s2 = g_srcs[beg + k + 2];
        int s3 = g_srcs[beg + k + 3];
        ACC(a, s0); ACC(a1, s1); ACC(a, s2); ACC(a1, s3);
    }
    for (; k < cnt; k++) ACC(a, g_srcs[beg + k]);
    a.x += a1.x; a.y += a1.y; a.z += a1.z; a.w += a1.w;
#undef ACC

    float dv = g_dinv[row];
    float4 bb = ((const float4*)bias)[lane];
    a.x = fmaxf(fmaf(a.x, dv, bb.x), 0.f);
    a.y = fmaxf(fmaf(a.y, dv, bb.y), 0.f);
    a.z = fmaxf(fmaf(a.z, dv, bb.z), 0.f);
    a.w = fmaxf(fmaf(a.w, dv, bb.w), 0.f);

    if (!do_pool) {
        __half2 h0 = __floats2half2_rn(a.x, a.y);
        __half2 h1 = __floats2half2_rn(a.z, a.w);
        uint2 st; st.x = *(u32*)&h0; st.y = *(u32*)&h1;
        *(uint2*)(g_hh + (size_t)row * HID + lane * 4) = st;
    } else {
        int b = fetch_idx(batch, (size_t)row, g_ba64);
        float* p = g_sum + b * 128 + lane * 4;
        atomicAdd(p + 0, a.x);
        atomicAdd(p + 1, a.y);
        atomicAdd(p + 2, a.z);
        atomicAdd(p + 3, a.w);
        if (lane == 0) atomicAdd(&g_cnt[b], 1.0f);
    }
}

// ---------------- MLP head ------------------------------------------------------
__global__ __launch_bounds__(128)
void head_kernel(const float* __restrict__ meta,
                 const float* __restrict__ Wh1, const float* __restrict__ bh1,
                 const float* __restrict__ Wh2, const float* __restrict__ bh2,
                 float* __restrict__ out)
{
    int b = blockIdx.x;
    int j = threadIdx.x;
    __shared__ float zin[HID + METAD];
    __shared__ float red[128];

    float inv = 1.0f / fmaxf(g_cnt[b], 1.0f);
    zin[j] = g_sum[b * HID + j] * inv;
    if (j < METAD) zin[HID + j] = meta[b * METAD + j];
    __syncthreads();

    float acc = bh1[j];
#pragma unroll
    for (int k = 0; k < HID + METAD; k++)
        acc = fmaf(zin[k], Wh1[k * HID + j], acc);
    red[j] = fmaxf(acc, 0.0f) * Wh2[j];
    __syncthreads();
#pragma unroll
    for (int s = 64; s > 0; s >>= 1) {
        if (j < s) red[j] += red[j + s];
        __syncthreads();
    }
    if (j == 0) out[b] = red[0] + bh2[0];
}

// --------------------------------------------------------------------------------
extern "C" void kernel_launch(void* const* d_in, const int* in_sizes, int n_in,
                              void* d_out, int out_size)
{
    const float* x     = (const float*)d_in[0];
    const int*   ei    = (const int*)d_in[1];
    const int*   batch = (const int*)d_in[2];
    const float* meta  = (const float*)d_in[3];
    const float* W1 = (const float*)d_in[4];  const float* b1 = (const float*)d_in[5];
    const float* W2 = (const float*)d_in[6];  const float* b2 = (const float*)d_in[7];
    const float* W3 = (const float*)d_in[8];  const float* b3 = (const float*)d_in[9];
    const float* Wh1 = (const float*)d_in[10]; const float* bh1 = (const float*)d_in[11];
    const float* Wh2 = (const float*)d_in[12]; const float* bh2 = (const float*)d_in[13];
    float* out = (float*)d_out;

    int N = in_sizes[0] / HID;
    int E = in_sizes[1] / 2;
    int B = in_sizes[3] / METAD;

    const int DSM = 2 * 128 * PITCH * (int)sizeof(__half);   // 69632
    cudaFuncSetAttribute(gemm_kernel, cudaFuncAttributeMaxDynamicSharedMemorySize, DSM);

    int initN = (N > B * HID) ? N : B * HID;
    init_kernel<<<(initN + 255) / 256, 256>>>(ei, batch, E, N, B);
    hist_kernel<<<(E + 255) / 256, 256>>>(ei, E);

    int nscan = (N + 255) / 256;
    scan_block_kernel<<<nscan, 256>>>(N);
    scan_add_kernel  <<<nscan, 256>>>(N);
    fill_kernel      <<<(E + 255) / 256, 256>>>(ei, E);

    int gblocks = (N + 127) / 128;
    int wblocks = (int)(((long long)N * 32 + 255) / 256);

    gemm_kernel  <<<gblocks, 256, DSM>>>(x, W1, N, 0);
    gather_kernel<<<wblocks, 256>>>(b1, N, batch, 0);
    gemm_kernel  <<<gblocks, 256, DSM>>>(nullptr, W2, N, 1);
    gather_kernel<<<wblocks, 256>>>(b2, N, batch, 0);
    gemm_kernel  <<<gblocks, 256, DSM>>>(nullptr, W3, N, 1);
    gather_kernel<<<wblocks, 256>>>(b3, N, batch, 1);

    head_kernel<<<B, 128>>>(meta, Wh1, bh1, Wh2, bh2, out);
}